// round 8
// baseline (speedup 1.0000x reference)
#include <cuda_runtime.h>
#include <math.h>
#include <stdint.h>

#define Bz 32
#define Tz 128
#define Vz 16000
#define Ez 512
#define Hz 1024
#define Fz 2048
#define NBLK 128

// -------- scratch (static device globals; no runtime allocation) --------
__device__ float g_pooled[Bz * Fz];
__device__ float g_h0[Bz * Hz];
__device__ float g_h1[Bz * Hz];
__device__ float g_xW[Bz * Tz * 4 * Hz];   // input-gate preactivations
__device__ float g_hs[Bz * Tz * Hz];       // hidden states (tf32-rounded)
__device__ float g_Wv[Vz * Hz];            // Wv tf32-rounded
__device__ float g_embt[Vz * Ez];          // emb tf32-rounded
__device__ float g_Wih[4 * Hz * Ez];       // W_ih tf32-rounded
__device__ float g_bihh[4 * Hz];           // b_ih + b_hh
__device__ int   g_idx[Bz * Tz];
__device__ int   g_flags[NBLK];

__device__ __forceinline__ float sigmoidf_(float x) {
    return 1.0f / (1.0f + expf(-x));
}
__device__ __forceinline__ float round_tf32(float x) {
    uint32_t u;
    asm("cvt.rna.tf32.f32 %0, %1;" : "=r"(u) : "f"(x));
    return __uint_as_float(u);
}
__device__ __forceinline__ void cpasync16(void* dst, const void* src) {
    uint32_t d = (uint32_t)__cvta_generic_to_shared(dst);
    asm volatile("cp.async.cg.shared.global [%0], [%1], 16;" :: "r"(d), "l"(src));
}
__device__ __forceinline__ void cpasync_commit() { asm volatile("cp.async.commit_group;"); }
__device__ __forceinline__ void cpasync_wait0()  { asm volatile("cp.async.wait_group 0;"); }

__device__ __forceinline__ void mma_tf32(float* c, const uint32_t* a, const uint32_t* b) {
    asm volatile(
        "mma.sync.aligned.m16n8k8.row.col.f32.tf32.tf32.f32 "
        "{%0,%1,%2,%3}, {%4,%5,%6,%7}, {%8,%9}, {%0,%1,%2,%3};"
        : "+f"(c[0]), "+f"(c[1]), "+f"(c[2]), "+f"(c[3])
        : "r"(a[0]), "r"(a[1]), "r"(a[2]), "r"(a[3]), "r"(b[0]), "r"(b[1]));
}

// ==================== launch 0: fused small prep ====================
__global__ void prep_kernel(const float* __restrict__ features,
                            const int* __restrict__ reports,
                            const float* __restrict__ b_ih,
                            const float* __restrict__ b_hh) {
    int n = blockIdx.x * blockDim.x + threadIdx.x;   // 65536 threads
    if (n < Bz * Fz) {
        const float* p = features + (size_t)n * 49;
        float s = 0.f;
#pragma unroll
        for (int i = 0; i < 49; i++) s += p[i];
        g_pooled[n] = s * (1.0f / 49.0f);
    }
    if (n < Bz * Tz) {
        int t = n & (Tz - 1);
        g_idx[n] = (t == 0) ? 1 : reports[n - 1];    // START_IDX = 1
    }
    if (n < 4 * Hz) g_bihh[n] = b_ih[n] + b_hh[n];
    if (n < NBLK) g_flags[n] = 0;
}

// ==================== launch 1: fused tf32 rounding (float4) ====================
__global__ void round_all_kernel(const float4* __restrict__ Wv,
                                 const float4* __restrict__ emb,
                                 const float4* __restrict__ Wih) {
    int i = blockIdx.x * blockDim.x + threadIdx.x;
    const int n1 = Vz * Hz / 4, n2 = Vz * Ez / 4, n3 = 4 * Hz * Ez / 4;
    float4 v;
    float4* dst;
    const float4* src;
    if (i < n1)            { src = Wv;  dst = (float4*)g_Wv;  }
    else if ((i -= n1) < n2) { src = emb; dst = (float4*)g_embt; }
    else if ((i -= n2) < n3) { src = Wih; dst = (float4*)g_Wih; }
    else return;
    v = src[i];
    v.x = round_tf32(v.x); v.y = round_tf32(v.y);
    v.z = round_tf32(v.z); v.w = round_tf32(v.w);
    dst[i] = v;
}

// ==================== TF32 tensor-core GEMM (launches 2 and 4) ====================
#define GROW 24
#define GEMM_SMEM (size_t)(4 * 128 * GROW * sizeof(float))

template<int MODE>
__global__ __launch_bounds__(256)
void gemm_tf32_kernel(const float* __restrict__ bias, float* __restrict__ outp)
{
    extern __shared__ float psm[];
    float* Asm = psm;
    float* Bsm = psm + 2 * 128 * GROW;

    constexpr int K = (MODE == 0) ? Ez : Hz;
    constexpr int N = (MODE == 0) ? 4 * Hz : Vz;
    const float* A  = (MODE == 0) ? g_embt : g_hs;
    const float* Bw = (MODE == 0) ? g_Wih : g_Wv;
    float* C        = (MODE == 0) ? g_xW : outp;
    const float* bias_p = (MODE == 0) ? g_bihh : bias;

    int tid = threadIdx.x;
    int m0 = blockIdx.x * 128;
    int n0 = blockIdx.y * 128;

    int wid = tid >> 5, lane = tid & 31;
    int wm = (wid >> 2) * 64;
    int wn = (wid & 3) * 32;
    int gid = lane >> 2, tig = lane & 3;

    float acc[4][4][4];
#pragma unroll
    for (int i = 0; i < 4; i++)
#pragma unroll
        for (int j = 0; j < 4; j++)
#pragma unroll
            for (int q = 0; q < 4; q++) acc[i][j][q] = 0.f;

    int ldr = tid >> 2;
    int ldc = (tid & 3) * 4;

    const float* aRow0;
    const float* aRow1;
    if (MODE == 0) {
        aRow0 = A + (size_t)g_idx[m0 + ldr] * K;
        aRow1 = A + (size_t)g_idx[m0 + ldr + 64] * K;
    } else {
        aRow0 = A + (size_t)(m0 + ldr) * K;
        aRow1 = aRow0 + (size_t)64 * K;
    }
    const float* bRow0 = Bw + (size_t)(n0 + ldr) * K;
    const float* bRow1 = bRow0 + (size_t)64 * K;

    const int NT = K / 16;

    cpasync16(&Asm[ldr * GROW + ldc],        aRow0 + ldc);
    cpasync16(&Asm[(ldr + 64) * GROW + ldc], aRow1 + ldc);
    cpasync16(&Bsm[ldr * GROW + ldc],        bRow0 + ldc);
    cpasync16(&Bsm[(ldr + 64) * GROW + ldc], bRow1 + ldc);
    cpasync_commit();

    for (int t = 0; t < NT; t++) {
        cpasync_wait0();
        __syncthreads();
        if (t + 1 < NT) {
            int nb = ((t + 1) & 1) * 128 * GROW;
            int k0 = (t + 1) * 16 + ldc;
            cpasync16(&Asm[nb + ldr * GROW + ldc],        aRow0 + k0);
            cpasync16(&Asm[nb + (ldr + 64) * GROW + ldc], aRow1 + k0);
            cpasync16(&Bsm[nb + ldr * GROW + ldc],        bRow0 + k0);
            cpasync16(&Bsm[nb + (ldr + 64) * GROW + ldc], bRow1 + k0);
            cpasync_commit();
        }
        int cb = (t & 1) * 128 * GROW;
#pragma unroll
        for (int ks = 0; ks < 2; ks++) {
            int kk = ks * 8 + 2 * tig;
            uint32_t a[4][4], b[4][2];
#pragma unroll
            for (int i = 0; i < 4; i++) {
                int r = wm + i * 16 + gid;
                float2 av0 = *(const float2*)(&Asm[cb + r * GROW + kk]);
                float2 av1 = *(const float2*)(&Asm[cb + (r + 8) * GROW + kk]);
                a[i][0] = __float_as_uint(av0.x);
                a[i][1] = __float_as_uint(av1.x);
                a[i][2] = __float_as_uint(av0.y);
                a[i][3] = __float_as_uint(av1.y);
            }
#pragma unroll
            for (int j = 0; j < 4; j++) {
                int n = wn + j * 8 + gid;
                float2 bv2 = *(const float2*)(&Bsm[cb + n * GROW + kk]);
                b[j][0] = __float_as_uint(bv2.x);
                b[j][1] = __float_as_uint(bv2.y);
            }
#pragma unroll
            for (int i = 0; i < 4; i++)
#pragma unroll
                for (int j = 0; j < 4; j++)
                    mma_tf32(acc[i][j], a[i], b[j]);
        }
        __syncthreads();
    }

#pragma unroll
    for (int j = 0; j < 4; j++) {
        int col = n0 + wn + j * 8 + tig * 2;
        float2 bvv = *(const float2*)(bias_p + col);
#pragma unroll
        for (int i = 0; i < 4; i++) {
            int r = m0 + wm + i * 16 + gid;
            float2 v0 = make_float2(acc[i][j][0] + bvv.x, acc[i][j][1] + bvv.y);
            float2 v1 = make_float2(acc[i][j][2] + bvv.x, acc[i][j][3] + bvv.y);
            *(float2*)(C + (size_t)r * N + col)       = v0;
            *(float2*)(C + (size_t)(r + 8) * N + col) = v1;
        }
    }
}

// ==================== launch 3 (ncu-captured): persistent LSTM ====================
// 128 blocks x 256 thr, 1 block/SM. Block bx owns h cols [8bx, 8bx+8) = 32 gate-rows.
// W_hh fragments live in REGISTERS (128/thread). h staged per step in ONE cp.async
// volley (128 KB) into XOR-swizzled smem: granule (k4, b) -> hsm16[k4*32 + (b ^ 4*(k4&1))].
// a-frag float2 reads are then conflict-free LDS.64 in both half-warp phases.
// Warp w owns k slice [128w, 128w+128); 8-way cross-warp smem reduction.
//
// smem floats: h 32768 (128KB) | red 8*32*36 = 9216 | gs 32*36 = 1152  -> ~169 KB
#define SMEM_LSTM (size_t)((32768 + 9216 + 1152) * sizeof(float))

__global__ __launch_bounds__(256)
void lstm_persistent(const float* __restrict__ Whh,
                     const float* __restrict__ fc_W,
                     const float* __restrict__ fc_b)
{
    extern __shared__ float sm[];
    float* hsm = sm;                       // [32768] swizzled h staging
    float* red = sm + 32768;               // [8][32][36]
    float* gs  = sm + 32768 + 9216;        // [32][36]

    int tid = threadIdx.x;
    int bx = blockIdx.x;
    int j0 = bx * 8;
    int lane = tid & 31;
    int w = tid >> 5;
    int gid = lane >> 2, tig = lane & 3;
    int tshift = tig >> 1;                 // k4 parity of this lane's slots
    int toff = 2 * (tig & 1);              // float offset within granule
    int xorv = 4 * tshift;                 // row swizzle
    int bb = tid >> 3, jj = tid & 7;

    // ---- prologue A: W_hh B-fragments -> registers (RNA tf32) ----
    // Warp w, frag (s, nt): b0 = W[nt*Hz + j0 + gid][128w + 8s + 2tig], b1 = same row, k+1
    uint32_t Bf[16][4][2];
#pragma unroll
    for (int s = 0; s < 16; s++) {
#pragma unroll
        for (int nt = 0; nt < 4; nt++) {
            const float* wrow = Whh + (size_t)(nt * Hz + j0 + gid) * Hz;
            float2 wv = *(const float2*)(wrow + 128 * w + 8 * s + 2 * tig);
            Bf[s][nt][0] = __float_as_uint(round_tf32(wv.x));
            Bf[s][nt][1] = __float_as_uint(round_tf32(wv.y));
        }
    }

    // ---- prologue B: init h0/c0 for this block's columns (warp-coop dots) ----
    for (int oo = 0; oo < 64; oo++) {
        int o = w * 64 + oo;
        int b = o & 31, r = o >> 5;
        int grow = (r < 8) ? (j0 + r) : (Hz + j0 + (r - 8));
        const float4* wp = (const float4*)(fc_W + (size_t)grow * Fz);
        const float4* pp = (const float4*)(g_pooled + (size_t)b * Fz);
        float4 s4 = make_float4(0.f, 0.f, 0.f, 0.f);
        for (int f = lane; f < Fz / 4; f += 32) {
            float4 wv = wp[f];
            float4 pv = pp[f];
            s4.x += wv.x * pv.x; s4.y += wv.y * pv.y;
            s4.z += wv.z * pv.z; s4.w += wv.w * pv.w;
        }
        float v = (s4.x + s4.y) + (s4.z + s4.w);
#pragma unroll
        for (int off = 16; off; off >>= 1) v += __shfl_xor_sync(0xffffffffu, v, off);
        if (lane == 0) {
            v += fc_b[grow];
            if (r < 8) __stcg(&g_h0[b * Hz + j0 + r], v);
            else       gs[b * 36 + (r - 8)] = v;
        }
    }
    __syncthreads();
    float c_reg = gs[bb * 36 + jj];

    // grid barrier: all h0 visible
    __threadfence();
    __syncthreads();
    if (tid == 0) atomicExch(&g_flags[bx], 1);
    if (tid < NBLK) {
        while (((volatile int*)g_flags)[tid] < 1) __nanosleep(32);
    }
    __syncthreads();

    // ---- 128 timesteps ----
    for (int t = 0; t < Tz; t++) {
        const float* h_in  = (t & 1) ? g_h1 : g_h0;
        float*       h_out = (t & 1) ? g_h0 : g_h1;

        size_t gbase = ((size_t)bb * Tz + t) * (4 * Hz);
        float xi = __ldcs(&g_xW[gbase + 0 * Hz + j0 + jj]);
        float xf = __ldcs(&g_xW[gbase + 1 * Hz + j0 + jj]);
        float xg = __ldcs(&g_xW[gbase + 2 * Hz + j0 + jj]);
        float xo = __ldcs(&g_xW[gbase + 3 * Hz + j0 + jj]);

        // single-volley stage of all h: granule (k4, b); b = i, k4 = tid (coalesced)
#pragma unroll
        for (int i = 0; i < 32; i++) {
            int k4 = tid;
            int b = i;
            int bs = b ^ (4 * (k4 & 1));
            cpasync16(hsm + k4 * 128 + bs * 4, h_in + b * Hz + k4 * 4);
        }
        cpasync_commit();

        float acc[2][4][4];
#pragma unroll
        for (int mt = 0; mt < 2; mt++)
#pragma unroll
            for (int nt = 0; nt < 4; nt++)
#pragma unroll
                for (int q = 0; q < 4; q++) acc[mt][nt][q] = 0.f;

        cpasync_wait0();
        __syncthreads();

#pragma unroll
        for (int s = 0; s < 16; s++) {
            int k4 = 32 * w + 2 * s + tshift;
            const float* base = hsm + k4 * 128 + toff;
            uint32_t a[2][4];
#pragma unroll
            for (int mt = 0; mt < 2; mt++) {
                int r0 = mt * 16 + gid;
                float2 a02 = *(const float2*)(base + ((r0 ^ xorv) * 4));
                float2 a13 = *(const float2*)(base + (((r0 + 8) ^ xorv) * 4));
                a[mt][0] = __float_as_uint(a02.x);
                a[mt][1] = __float_as_uint(a13.x);
                a[mt][2] = __float_as_uint(a02.y);
                a[mt][3] = __float_as_uint(a13.y);
            }
#pragma unroll
            for (int nt = 0; nt < 4; nt++) {
                mma_tf32(acc[0][nt], a[0], Bf[s][nt]);
                mma_tf32(acc[1][nt], a[1], Bf[s][nt]);
            }
        }

        // ---- cross-warp reduction ----
        __syncthreads();
#pragma unroll
        for (int mt = 0; mt < 2; mt++) {
#pragma unroll
            for (int nt = 0; nt < 4; nt++) {
                int row0 = mt * 16 + gid;
                int n = nt * 8 + 2 * tig;
                *(float2*)(red + (w * 32 + row0) * 36 + n) =
                    make_float2(acc[mt][nt][0], acc[mt][nt][1]);
                *(float2*)(red + (w * 32 + row0 + 8) * 36 + n) =
                    make_float2(acc[mt][nt][2], acc[mt][nt][3]);
            }
        }
        __syncthreads();
        {
            int b = tid >> 3, n4 = (tid & 7) * 4;
            float4 sum = make_float4(0.f, 0.f, 0.f, 0.f);
#pragma unroll
            for (int ww = 0; ww < 8; ww++) {
                float4 v = *(const float4*)(red + (ww * 32 + b) * 36 + n4);
                sum.x += v.x; sum.y += v.y; sum.z += v.z; sum.w += v.w;
            }
            *(float4*)(gs + b * 36 + n4) = sum;
        }
        __syncthreads();

        // ---- elementwise gate update ----
        float gi = gs[bb * 36 +  0 + jj] + xi;
        float gf = gs[bb * 36 +  8 + jj] + xf;
        float gg = gs[bb * 36 + 16 + jj] + xg;
        float go = gs[bb * 36 + 24 + jj] + xo;

        float cn = sigmoidf_(gf) * c_reg + sigmoidf_(gi) * tanhf(gg);
        float hn = sigmoidf_(go) * tanhf(cn);
        c_reg = cn;
        float hr = round_tf32(hn);
        __stcg(h_out + bb * Hz + j0 + jj, hr);
        g_hs[((size_t)bb * Tz + t) * Hz + j0 + jj] = hr;

        // ---- grid barrier ----
        __threadfence();
        __syncthreads();
        if (tid == 0) atomicExch(&g_flags[bx], t + 2);
        if (tid < NBLK) {
            while (((volatile int*)g_flags)[tid] < t + 2) __nanosleep(32);
        }
        __syncthreads();
    }
}

// ==================== launcher ====================
extern "C" void kernel_launch(void* const* d_in, const int* in_sizes, int n_in,
                              void* d_out, int out_size) {
    const float* features = (const float*)d_in[0];
    const int*   reports  = (const int*)d_in[1];
    const float* fc_W     = (const float*)d_in[2];
    const float* fc_b     = (const float*)d_in[3];
    const float* emb      = (const float*)d_in[4];
    const float* W_ih     = (const float*)d_in[5];
    const float* W_hh     = (const float*)d_in[6];
    const float* b_ih     = (const float*)d_in[7];
    const float* b_hh     = (const float*)d_in[8];
    const float* Wv       = (const float*)d_in[9];
    const float* bv       = (const float*)d_in[10];
    float* out = (float*)d_out;

    (void)in_sizes; (void)n_in; (void)out_size;

    cudaFuncSetAttribute(lstm_persistent,
                         cudaFuncAttributeMaxDynamicSharedMemorySize, (int)SMEM_LSTM);
    cudaFuncSetAttribute(gemm_tf32_kernel<0>,
                         cudaFuncAttributeMaxDynamicSharedMemorySize, (int)GEMM_SMEM);
    cudaFuncSetAttribute(gemm_tf32_kernel<1>,
                         cudaFuncAttributeMaxDynamicSharedMemorySize, (int)GEMM_SMEM);

    // launch 0: fused prep (pool + idx + bias + flags)
    prep_kernel<<<(Bz * Fz + 255) / 256, 256>>>(features, reports, b_ih, b_hh);

    // launch 1: fused tf32 rounding (Wv, emb, W_ih), float4
    {
        int n = (Vz * Hz + Vz * Ez + 4 * Hz * Ez) / 4;
        round_all_kernel<<<(n + 255) / 256, 256>>>((const float4*)Wv,
                                                   (const float4*)emb,
                                                   (const float4*)W_ih);
    }

    // launch 2: input GEMM  xW = emb[idx] @ W_ih^T + (b_ih + b_hh)
    gemm_tf32_kernel<0><<<dim3(Bz * Tz / 128, 4 * Hz / 128), 256, GEMM_SMEM>>>(nullptr, nullptr);

    // launch 3 (ncu-captured): persistent LSTM (init + 128 timesteps)
    lstm_persistent<<<NBLK, 256, SMEM_LSTM>>>(W_hh, fc_W, fc_b);

    // launch 4: projection  out = hs @ Wv^T + bv
    gemm_tf32_kernel<1><<<dim3(Bz * Tz / 128, Vz / 128), 256, GEMM_SMEM>>>(bv, out);
}

// round 9
// speedup vs baseline: 1.0806x; 1.0806x over previous
#include <cuda_runtime.h>
#include <math.h>
#include <stdint.h>

#define Bz 32
#define Tz 128
#define Vz 16000
#define Ez 512
#define Hz 1024
#define Fz 2048
#define NBLK 128

// -------- scratch (static device globals; no runtime allocation) --------
__device__ float g_pooled[Bz * Fz];
__device__ float g_h0[Bz * Hz];
__device__ float g_h1[Bz * Hz];
__device__ float g_xW[Bz * Tz * 4 * Hz];   // input-gate preactivations
__device__ float g_hs[Bz * Tz * Hz];       // hidden states (tf32-rounded)
__device__ float g_Wv[Vz * Hz];            // Wv tf32-rounded
__device__ float g_embt[Vz * Ez];          // emb tf32-rounded
__device__ float g_Wih[4 * Hz * Ez];       // W_ih tf32-rounded
__device__ float g_bihh[4 * Hz];           // b_ih + b_hh
__device__ int   g_idx[Bz * Tz];
__device__ int   g_flags[NBLK];

__device__ __forceinline__ float sigmoidf_(float x) {
    return 1.0f / (1.0f + expf(-x));
}
__device__ __forceinline__ float round_tf32(float x) {
    uint32_t u;
    asm("cvt.rna.tf32.f32 %0, %1;" : "=r"(u) : "f"(x));
    return __uint_as_float(u);
}
__device__ __forceinline__ void cpasync16(void* dst, const void* src) {
    uint32_t d = (uint32_t)__cvta_generic_to_shared(dst);
    asm volatile("cp.async.cg.shared.global [%0], [%1], 16;" :: "r"(d), "l"(src));
}
__device__ __forceinline__ void cpasync_commit() { asm volatile("cp.async.commit_group;"); }
__device__ __forceinline__ void cpasync_wait0()  { asm volatile("cp.async.wait_group 0;"); }

__device__ __forceinline__ void mma_tf32(float* c, const uint32_t* a, const uint32_t* b) {
    asm volatile(
        "mma.sync.aligned.m16n8k8.row.col.f32.tf32.tf32.f32 "
        "{%0,%1,%2,%3}, {%4,%5,%6,%7}, {%8,%9}, {%0,%1,%2,%3};"
        : "+f"(c[0]), "+f"(c[1]), "+f"(c[2]), "+f"(c[3])
        : "r"(a[0]), "r"(a[1]), "r"(a[2]), "r"(a[3]), "r"(b[0]), "r"(b[1]));
}

// ==================== launch 0: fused small prep ====================
__global__ void prep_kernel(const float* __restrict__ features,
                            const int* __restrict__ reports,
                            const float* __restrict__ b_ih,
                            const float* __restrict__ b_hh) {
    int n = blockIdx.x * blockDim.x + threadIdx.x;   // 65536 threads
    if (n < Bz * Fz) {
        const float* p = features + (size_t)n * 49;
        float s = 0.f;
#pragma unroll
        for (int i = 0; i < 49; i++) s += p[i];
        g_pooled[n] = s * (1.0f / 49.0f);
    }
    if (n < Bz * Tz) {
        int t = n & (Tz - 1);
        g_idx[n] = (t == 0) ? 1 : reports[n - 1];    // START_IDX = 1
    }
    if (n < 4 * Hz) g_bihh[n] = b_ih[n] + b_hh[n];
    if (n < NBLK) g_flags[n] = 0;
}

// ==================== launch 1: fused tf32 rounding (float4) ====================
__global__ void round_all_kernel(const float4* __restrict__ Wv,
                                 const float4* __restrict__ emb,
                                 const float4* __restrict__ Wih) {
    int i = blockIdx.x * blockDim.x + threadIdx.x;
    const int n1 = Vz * Hz / 4, n2 = Vz * Ez / 4, n3 = 4 * Hz * Ez / 4;
    float4 v;
    float4* dst;
    const float4* src;
    if (i < n1)            { src = Wv;  dst = (float4*)g_Wv;  }
    else if ((i -= n1) < n2) { src = emb; dst = (float4*)g_embt; }
    else if ((i -= n2) < n3) { src = Wih; dst = (float4*)g_Wih; }
    else return;
    v = src[i];
    v.x = round_tf32(v.x); v.y = round_tf32(v.y);
    v.z = round_tf32(v.z); v.w = round_tf32(v.w);
    dst[i] = v;
}

// ==================== TF32 tensor-core GEMM (launches 2 and 4) ====================
#define GROW 24
#define GEMM_SMEM (size_t)(4 * 128 * GROW * sizeof(float))

template<int MODE>
__global__ __launch_bounds__(256)
void gemm_tf32_kernel(const float* __restrict__ bias, float* __restrict__ outp)
{
    extern __shared__ float psm[];
    float* Asm = psm;
    float* Bsm = psm + 2 * 128 * GROW;

    constexpr int K = (MODE == 0) ? Ez : Hz;
    constexpr int N = (MODE == 0) ? 4 * Hz : Vz;
    const float* A  = (MODE == 0) ? g_embt : g_hs;
    const float* Bw = (MODE == 0) ? g_Wih : g_Wv;
    float* C        = (MODE == 0) ? g_xW : outp;
    const float* bias_p = (MODE == 0) ? g_bihh : bias;

    int tid = threadIdx.x;
    int m0 = blockIdx.x * 128;
    int n0 = blockIdx.y * 128;

    int wid = tid >> 5, lane = tid & 31;
    int wm = (wid >> 2) * 64;
    int wn = (wid & 3) * 32;
    int gid = lane >> 2, tig = lane & 3;

    float acc[4][4][4];
#pragma unroll
    for (int i = 0; i < 4; i++)
#pragma unroll
        for (int j = 0; j < 4; j++)
#pragma unroll
            for (int q = 0; q < 4; q++) acc[i][j][q] = 0.f;

    int ldr = tid >> 2;
    int ldc = (tid & 3) * 4;

    const float* aRow0;
    const float* aRow1;
    if (MODE == 0) {
        aRow0 = A + (size_t)g_idx[m0 + ldr] * K;
        aRow1 = A + (size_t)g_idx[m0 + ldr + 64] * K;
    } else {
        aRow0 = A + (size_t)(m0 + ldr) * K;
        aRow1 = aRow0 + (size_t)64 * K;
    }
    const float* bRow0 = Bw + (size_t)(n0 + ldr) * K;
    const float* bRow1 = bRow0 + (size_t)64 * K;

    const int NT = K / 16;

    cpasync16(&Asm[ldr * GROW + ldc],        aRow0 + ldc);
    cpasync16(&Asm[(ldr + 64) * GROW + ldc], aRow1 + ldc);
    cpasync16(&Bsm[ldr * GROW + ldc],        bRow0 + ldc);
    cpasync16(&Bsm[(ldr + 64) * GROW + ldc], bRow1 + ldc);
    cpasync_commit();

    for (int t = 0; t < NT; t++) {
        cpasync_wait0();
        __syncthreads();
        if (t + 1 < NT) {
            int nb = ((t + 1) & 1) * 128 * GROW;
            int k0 = (t + 1) * 16 + ldc;
            cpasync16(&Asm[nb + ldr * GROW + ldc],        aRow0 + k0);
            cpasync16(&Asm[nb + (ldr + 64) * GROW + ldc], aRow1 + k0);
            cpasync16(&Bsm[nb + ldr * GROW + ldc],        bRow0 + k0);
            cpasync16(&Bsm[nb + (ldr + 64) * GROW + ldc], bRow1 + k0);
            cpasync_commit();
        }
        int cb = (t & 1) * 128 * GROW;
#pragma unroll
        for (int ks = 0; ks < 2; ks++) {
            int kk = ks * 8 + 2 * tig;
            uint32_t a[4][4], b[4][2];
#pragma unroll
            for (int i = 0; i < 4; i++) {
                int r = wm + i * 16 + gid;
                float2 av0 = *(const float2*)(&Asm[cb + r * GROW + kk]);
                float2 av1 = *(const float2*)(&Asm[cb + (r + 8) * GROW + kk]);
                a[i][0] = __float_as_uint(av0.x);
                a[i][1] = __float_as_uint(av1.x);
                a[i][2] = __float_as_uint(av0.y);
                a[i][3] = __float_as_uint(av1.y);
            }
#pragma unroll
            for (int j = 0; j < 4; j++) {
                int n = wn + j * 8 + gid;
                float2 bv2 = *(const float2*)(&Bsm[cb + n * GROW + kk]);
                b[j][0] = __float_as_uint(bv2.x);
                b[j][1] = __float_as_uint(bv2.y);
            }
#pragma unroll
            for (int i = 0; i < 4; i++)
#pragma unroll
                for (int j = 0; j < 4; j++)
                    mma_tf32(acc[i][j], a[i], b[j]);
        }
        __syncthreads();
    }

#pragma unroll
    for (int j = 0; j < 4; j++) {
        int col = n0 + wn + j * 8 + tig * 2;
        float2 bvv = *(const float2*)(bias_p + col);
#pragma unroll
        for (int i = 0; i < 4; i++) {
            int r = m0 + wm + i * 16 + gid;
            float2 v0 = make_float2(acc[i][j][0] + bvv.x, acc[i][j][1] + bvv.y);
            float2 v1 = make_float2(acc[i][j][2] + bvv.x, acc[i][j][3] + bvv.y);
            *(float2*)(C + (size_t)r * N + col)       = v0;
            *(float2*)(C + (size_t)(r + 8) * N + col) = v1;
        }
    }
}

// ==================== launch 3 (ncu-captured): persistent LSTM ====================
// 128 blocks x 256 thr, 1 block/SM. Block bx owns h cols [8bx, 8bx+8) = 32 gate-rows.
// W_hh fragments in REGISTERS (128/thread). h staged per step in ONE cp.async volley.
// smem h layout: granule (k4, b) -> hsm[k4*HS4 + (b ^ 4*(k4&1))*4], HS4 = 132 floats.
//   writes: lane l (k4 = 32w+l) -> byte addr mod 512 = 16*(l + xor-term), tiles all
//   128 banks exactly once -> CONFLICT-FREE (this was R7's 32-way-conflict bug).
//   reads: a-frag LDS.64, at worst 2-way conflicted.
// Warp w owns k slice [128w, 128w+128); 8-way cross-warp smem reduction.
#define HS4 132
#define SMEM_LSTM (size_t)((256 * HS4 + 9216 + 1152) * sizeof(float))

__global__ __launch_bounds__(256)
void lstm_persistent(const float* __restrict__ Whh,
                     const float* __restrict__ fc_W,
                     const float* __restrict__ fc_b)
{
    extern __shared__ float sm[];
    float* hsm = sm;                        // [256*HS4] swizzled h staging
    float* red = sm + 256 * HS4;            // [8][32][36]
    float* gs  = sm + 256 * HS4 + 9216;     // [32][36]

    int tid = threadIdx.x;
    int bx = blockIdx.x;
    int j0 = bx * 8;
    int lane = tid & 31;
    int w = tid >> 5;
    int gid = lane >> 2, tig = lane & 3;
    int tshift = tig >> 1;                  // k4 parity of this lane's slots
    int toff = 2 * (tig & 1);               // float offset within granule
    int xorv = 4 * tshift;                  // row swizzle (k4 = even + tshift)
    int bb = tid >> 3, jj = tid & 7;

    // ---- prologue A: W_hh B-fragments -> registers (RNA tf32) ----
    uint32_t Bf[16][4][2];
#pragma unroll
    for (int s = 0; s < 16; s++) {
#pragma unroll
        for (int nt = 0; nt < 4; nt++) {
            const float* wrow = Whh + (size_t)(nt * Hz + j0 + gid) * Hz;
            float2 wv = *(const float2*)(wrow + 128 * w + 8 * s + 2 * tig);
            Bf[s][nt][0] = __float_as_uint(round_tf32(wv.x));
            Bf[s][nt][1] = __float_as_uint(round_tf32(wv.y));
        }
    }

    // ---- prologue B: init h0/c0 for this block's columns (warp-coop dots) ----
    for (int oo = 0; oo < 64; oo++) {
        int o = w * 64 + oo;
        int b = o & 31, r = o >> 5;
        int grow = (r < 8) ? (j0 + r) : (Hz + j0 + (r - 8));
        const float4* wp = (const float4*)(fc_W + (size_t)grow * Fz);
        const float4* pp = (const float4*)(g_pooled + (size_t)b * Fz);
        float4 s4 = make_float4(0.f, 0.f, 0.f, 0.f);
        for (int f = lane; f < Fz / 4; f += 32) {
            float4 wv = wp[f];
            float4 pv = pp[f];
            s4.x += wv.x * pv.x; s4.y += wv.y * pv.y;
            s4.z += wv.z * pv.z; s4.w += wv.w * pv.w;
        }
        float v = (s4.x + s4.y) + (s4.z + s4.w);
#pragma unroll
        for (int off = 16; off; off >>= 1) v += __shfl_xor_sync(0xffffffffu, v, off);
        if (lane == 0) {
            v += fc_b[grow];
            if (r < 8) __stcg(&g_h0[b * Hz + j0 + r], v);
            else       gs[b * 36 + (r - 8)] = v;
        }
    }
    __syncthreads();
    float c_reg = gs[bb * 36 + jj];

    // grid barrier: all h0 visible
    __threadfence();
    __syncthreads();
    if (tid == 0) atomicExch(&g_flags[bx], 1);
    if (tid < NBLK) {
        while (((volatile int*)g_flags)[tid] < 1) __nanosleep(32);
    }
    __syncthreads();

    // ---- 128 timesteps ----
    for (int t = 0; t < Tz; t++) {
        const float* h_in  = (t & 1) ? g_h1 : g_h0;
        float*       h_out = (t & 1) ? g_h0 : g_h1;

        size_t gbase = ((size_t)bb * Tz + t) * (4 * Hz);
        float xi = __ldcs(&g_xW[gbase + 0 * Hz + j0 + jj]);
        float xf = __ldcs(&g_xW[gbase + 1 * Hz + j0 + jj]);
        float xg = __ldcs(&g_xW[gbase + 2 * Hz + j0 + jj]);
        float xo = __ldcs(&g_xW[gbase + 3 * Hz + j0 + jj]);

        // single-volley stage of all h: thread tid handles k4 = tid, loops over b.
        // Write addresses tile all banks (stride 528B) -> conflict-free.
#pragma unroll
        for (int i = 0; i < 32; i++) {
            int k4 = tid;
            int bs = i ^ (4 * (k4 & 1));
            cpasync16(hsm + k4 * HS4 + bs * 4, h_in + (size_t)i * Hz + k4 * 4);
        }
        cpasync_commit();

        float acc[2][4][4];
#pragma unroll
        for (int mt = 0; mt < 2; mt++)
#pragma unroll
            for (int nt = 0; nt < 4; nt++)
#pragma unroll
                for (int q = 0; q < 4; q++) acc[mt][nt][q] = 0.f;

        cpasync_wait0();
        __syncthreads();

#pragma unroll
        for (int s = 0; s < 16; s++) {
            int k4 = 32 * w + 2 * s + tshift;
            const float* base = hsm + k4 * HS4 + toff;
            uint32_t a[2][4];
#pragma unroll
            for (int mt = 0; mt < 2; mt++) {
                int r0 = mt * 16 + gid;
                float2 a02 = *(const float2*)(base + ((r0 ^ xorv) * 4));
                float2 a13 = *(const float2*)(base + (((r0 + 8) ^ xorv) * 4));
                a[mt][0] = __float_as_uint(a02.x);
                a[mt][1] = __float_as_uint(a13.x);
                a[mt][2] = __float_as_uint(a02.y);
                a[mt][3] = __float_as_uint(a13.y);
            }
#pragma unroll
            for (int nt = 0; nt < 4; nt++) {
                mma_tf32(acc[0][nt], a[0], Bf[s][nt]);
                mma_tf32(acc[1][nt], a[1], Bf[s][nt]);
            }
        }

        // ---- cross-warp reduction ----
        __syncthreads();
#pragma unroll
        for (int mt = 0; mt < 2; mt++) {
#pragma unroll
            for (int nt = 0; nt < 4; nt++) {
                int row0 = mt * 16 + gid;
                int n = nt * 8 + 2 * tig;
                *(float2*)(red + (w * 32 + row0) * 36 + n) =
                    make_float2(acc[mt][nt][0], acc[mt][nt][1]);
                *(float2*)(red + (w * 32 + row0 + 8) * 36 + n) =
                    make_float2(acc[mt][nt][2], acc[mt][nt][3]);
            }
        }
        __syncthreads();
        {
            int b = tid >> 3, n4 = (tid & 7) * 4;
            float4 sum = make_float4(0.f, 0.f, 0.f, 0.f);
#pragma unroll
            for (int ww = 0; ww < 8; ww++) {
                float4 v = *(const float4*)(red + (ww * 32 + b) * 36 + n4);
                sum.x += v.x; sum.y += v.y; sum.z += v.z; sum.w += v.w;
            }
            *(float4*)(gs + b * 36 + n4) = sum;
        }
        __syncthreads();

        // ---- elementwise gate update ----
        float gi = gs[bb * 36 +  0 + jj] + xi;
        float gf = gs[bb * 36 +  8 + jj] + xf;
        float gg = gs[bb * 36 + 16 + jj] + xg;
        float go = gs[bb * 36 + 24 + jj] + xo;

        float cn = sigmoidf_(gf) * c_reg + sigmoidf_(gi) * tanhf(gg);
        float hn = sigmoidf_(go) * tanhf(cn);
        c_reg = cn;
        float hr = round_tf32(hn);
        __stcg(h_out + bb * Hz + j0 + jj, hr);
        g_hs[((size_t)bb * Tz + t) * Hz + j0 + jj] = hr;

        // ---- grid barrier ----
        __threadfence();
        __syncthreads();
        if (tid == 0) atomicExch(&g_flags[bx], t + 2);
        if (tid < NBLK) {
            while (((volatile int*)g_flags)[tid] < t + 2) __nanosleep(32);
        }
        __syncthreads();
    }
}

// ==================== launcher ====================
extern "C" void kernel_launch(void* const* d_in, const int* in_sizes, int n_in,
                              void* d_out, int out_size) {
    const float* features = (const float*)d_in[0];
    const int*   reports  = (const int*)d_in[1];
    const float* fc_W     = (const float*)d_in[2];
    const float* fc_b     = (const float*)d_in[3];
    const float* emb      = (const float*)d_in[4];
    const float* W_ih     = (const float*)d_in[5];
    const float* W_hh     = (const float*)d_in[6];
    const float* b_ih     = (const float*)d_in[7];
    const float* b_hh     = (const float*)d_in[8];
    const float* Wv       = (const float*)d_in[9];
    const float* bv       = (const float*)d_in[10];
    float* out = (float*)d_out;

    (void)in_sizes; (void)n_in; (void)out_size;

    cudaFuncSetAttribute(lstm_persistent,
                         cudaFuncAttributeMaxDynamicSharedMemorySize, (int)SMEM_LSTM);
    cudaFuncSetAttribute(gemm_tf32_kernel<0>,
                         cudaFuncAttributeMaxDynamicSharedMemorySize, (int)GEMM_SMEM);
    cudaFuncSetAttribute(gemm_tf32_kernel<1>,
                         cudaFuncAttributeMaxDynamicSharedMemorySize, (int)GEMM_SMEM);

    // launch 0: fused prep (pool + idx + bias + flags)
    prep_kernel<<<(Bz * Fz + 255) / 256, 256>>>(features, reports, b_ih, b_hh);

    // launch 1: fused tf32 rounding (Wv, emb, W_ih), float4
    {
        int n = (Vz * Hz + Vz * Ez + 4 * Hz * Ez) / 4;
        round_all_kernel<<<(n + 255) / 256, 256>>>((const float4*)Wv,
                                                   (const float4*)emb,
                                                   (const float4*)W_ih);
    }

    // launch 2: input GEMM  xW = emb[idx] @ W_ih^T + (b_ih + b_hh)
    gemm_tf32_kernel<0><<<dim3(Bz * Tz / 128, 4 * Hz / 128), 256, GEMM_SMEM>>>(nullptr, nullptr);

    // launch 3 (ncu-captured): persistent LSTM (init + 128 timesteps)
    lstm_persistent<<<NBLK, 256, SMEM_LSTM>>>(W_hh, fc_W, fc_b);

    // launch 4: projection  out = hs @ Wv^T + bv
    gemm_tf32_kernel<1><<<dim3(Bz * Tz / 128, Vz / 128), 256, GEMM_SMEM>>>(bv, out);
}

// round 10
// speedup vs baseline: 1.5890x; 1.4704x over previous
#include <cuda_runtime.h>
#include <math.h>
#include <stdint.h>

#define Bz 32
#define Tz 128
#define Vz 16000
#define Ez 512
#define Hz 1024
#define Fz 2048
#define NBLK 128
#define HTS 40                            // hT row stride in floats (conflict-free banks)

// -------- scratch (static device globals; no runtime allocation) --------
__device__ float g_pooled[Bz * Fz];
__device__ float g_hT[2][Hz * HTS];        // transposed h ping-pong: hT[k*HTS + b]
__device__ float g_xW[Bz * Tz * 4 * Hz];   // input-gate preactivations
__device__ float g_hs[Bz * Tz * Hz];       // hidden states (tf32-rounded)
__device__ float g_Wv[Vz * Hz];            // Wv tf32-rounded
__device__ float g_embt[Vz * Ez];          // emb tf32-rounded
__device__ float g_Wih[4 * Hz * Ez];       // W_ih tf32-rounded
__device__ float g_bihh[4 * Hz];           // b_ih + b_hh
__device__ int   g_idx[Bz * Tz];
__device__ int   g_flags[NBLK];

__device__ __forceinline__ float sigmoidf_(float x) {
    return 1.0f / (1.0f + expf(-x));
}
__device__ __forceinline__ float round_tf32(float x) {
    uint32_t u;
    asm("cvt.rna.tf32.f32 %0, %1;" : "=r"(u) : "f"(x));
    return __uint_as_float(u);
}
__device__ __forceinline__ void cpasync16(void* dst, const void* src) {
    uint32_t d = (uint32_t)__cvta_generic_to_shared(dst);
    asm volatile("cp.async.cg.shared.global [%0], [%1], 16;" :: "r"(d), "l"(src));
}
__device__ __forceinline__ void cpasync_commit() { asm volatile("cp.async.commit_group;"); }
__device__ __forceinline__ void cpasync_wait0()  { asm volatile("cp.async.wait_group 0;"); }

__device__ __forceinline__ void mma_tf32(float* c, const uint32_t* a, const uint32_t* b) {
    asm volatile(
        "mma.sync.aligned.m16n8k8.row.col.f32.tf32.tf32.f32 "
        "{%0,%1,%2,%3}, {%4,%5,%6,%7}, {%8,%9}, {%0,%1,%2,%3};"
        : "+f"(c[0]), "+f"(c[1]), "+f"(c[2]), "+f"(c[3])
        : "r"(a[0]), "r"(a[1]), "r"(a[2]), "r"(a[3]), "r"(b[0]), "r"(b[1]));
}

// ---- mbarrier + bulk-copy helpers ----
__device__ __forceinline__ void mbar_init(uint32_t a, uint32_t cnt) {
    asm volatile("mbarrier.init.shared.b64 [%0], %1;" :: "r"(a), "r"(cnt) : "memory");
}
__device__ __forceinline__ void mbar_expect_tx(uint32_t a, uint32_t bytes) {
    asm volatile("mbarrier.arrive.expect_tx.shared.b64 _, [%0], %1;"
                 :: "r"(a), "r"(bytes) : "memory");
}
__device__ __forceinline__ void mbar_wait_parity(uint32_t a, uint32_t parity) {
    uint32_t done;
    asm volatile(
        "{\n\t.reg .pred p;\n\t"
        "mbarrier.try_wait.parity.acquire.cta.shared::cta.b64 p, [%1], %2;\n\t"
        "selp.b32 %0, 1, 0, p;\n\t}"
        : "=r"(done) : "r"(a), "r"(parity) : "memory");
    if (!done) {
        asm volatile(
            "{\n\t.reg .pred P1;\n\t"
            "WL_%=:\n\t"
            "mbarrier.try_wait.parity.acquire.cta.shared::cta.b64 P1, [%0], %1, 0x989680;\n\t"
            "@P1 bra.uni WD_%=;\n\t"
            "bra.uni WL_%=;\n\t"
            "WD_%=:\n\t}"
            :: "r"(a), "r"(parity) : "memory");
    }
}
__device__ __forceinline__ void bulk_g2s(uint32_t dst_smem, const void* src,
                                         uint32_t bytes, uint32_t mbar) {
    asm volatile(
        "cp.async.bulk.shared::cta.global.mbarrier::complete_tx::bytes [%0], [%1], %2, [%3];"
        :: "r"(dst_smem), "l"(src), "r"(bytes), "r"(mbar) : "memory");
}

// ==================== launch 0: fused small prep ====================
__global__ void prep_kernel(const float* __restrict__ features,
                            const int* __restrict__ reports,
                            const float* __restrict__ b_ih,
                            const float* __restrict__ b_hh) {
    int n = blockIdx.x * blockDim.x + threadIdx.x;   // 65536 threads
    if (n < Bz * Fz) {
        const float* p = features + (size_t)n * 49;
        float s = 0.f;
#pragma unroll
        for (int i = 0; i < 49; i++) s += p[i];
        g_pooled[n] = s * (1.0f / 49.0f);
    }
    if (n < Bz * Tz) {
        int t = n & (Tz - 1);
        g_idx[n] = (t == 0) ? 1 : reports[n - 1];    // START_IDX = 1
    }
    if (n < 4 * Hz) g_bihh[n] = b_ih[n] + b_hh[n];
    if (n < NBLK) g_flags[n] = 0;
}

// ==================== launch 1: fused tf32 rounding (float4) ====================
__global__ void round_all_kernel(const float4* __restrict__ Wv,
                                 const float4* __restrict__ emb,
                                 const float4* __restrict__ Wih) {
    int i = blockIdx.x * blockDim.x + threadIdx.x;
    const int n1 = Vz * Hz / 4, n2 = Vz * Ez / 4, n3 = 4 * Hz * Ez / 4;
    float4 v;
    float4* dst;
    const float4* src;
    if (i < n1)            { src = Wv;  dst = (float4*)g_Wv;  }
    else if ((i -= n1) < n2) { src = emb; dst = (float4*)g_embt; }
    else if ((i -= n2) < n3) { src = Wih; dst = (float4*)g_Wih; }
    else return;
    v = src[i];
    v.x = round_tf32(v.x); v.y = round_tf32(v.y);
    v.z = round_tf32(v.z); v.w = round_tf32(v.w);
    dst[i] = v;
}

// ==================== TF32 tensor-core GEMM (launches 2 and 4) ====================
#define GROW 24
#define GEMM_SMEM (size_t)(4 * 128 * GROW * sizeof(float))

template<int MODE>
__global__ __launch_bounds__(256)
void gemm_tf32_kernel(const float* __restrict__ bias, float* __restrict__ outp)
{
    extern __shared__ float psm[];
    float* Asm = psm;
    float* Bsm = psm + 2 * 128 * GROW;

    constexpr int K = (MODE == 0) ? Ez : Hz;
    constexpr int N = (MODE == 0) ? 4 * Hz : Vz;
    const float* A  = (MODE == 0) ? g_embt : g_hs;
    const float* Bw = (MODE == 0) ? g_Wih : g_Wv;
    float* C        = (MODE == 0) ? g_xW : outp;
    const float* bias_p = (MODE == 0) ? g_bihh : bias;

    int tid = threadIdx.x;
    int m0 = blockIdx.x * 128;
    int n0 = blockIdx.y * 128;

    int wid = tid >> 5, lane = tid & 31;
    int wm = (wid >> 2) * 64;
    int wn = (wid & 3) * 32;
    int gid = lane >> 2, tig = lane & 3;

    float acc[4][4][4];
#pragma unroll
    for (int i = 0; i < 4; i++)
#pragma unroll
        for (int j = 0; j < 4; j++)
#pragma unroll
            for (int q = 0; q < 4; q++) acc[i][j][q] = 0.f;

    int ldr = tid >> 2;
    int ldc = (tid & 3) * 4;

    const float* aRow0;
    const float* aRow1;
    if (MODE == 0) {
        aRow0 = A + (size_t)g_idx[m0 + ldr] * K;
        aRow1 = A + (size_t)g_idx[m0 + ldr + 64] * K;
    } else {
        aRow0 = A + (size_t)(m0 + ldr) * K;
        aRow1 = aRow0 + (size_t)64 * K;
    }
    const float* bRow0 = Bw + (size_t)(n0 + ldr) * K;
    const float* bRow1 = bRow0 + (size_t)64 * K;

    const int NT = K / 16;

    cpasync16(&Asm[ldr * GROW + ldc],        aRow0 + ldc);
    cpasync16(&Asm[(ldr + 64) * GROW + ldc], aRow1 + ldc);
    cpasync16(&Bsm[ldr * GROW + ldc],        bRow0 + ldc);
    cpasync16(&Bsm[(ldr + 64) * GROW + ldc], bRow1 + ldc);
    cpasync_commit();

    for (int t = 0; t < NT; t++) {
        cpasync_wait0();
        __syncthreads();
        if (t + 1 < NT) {
            int nb = ((t + 1) & 1) * 128 * GROW;
            int k0 = (t + 1) * 16 + ldc;
            cpasync16(&Asm[nb + ldr * GROW + ldc],        aRow0 + k0);
            cpasync16(&Asm[nb + (ldr + 64) * GROW + ldc], aRow1 + k0);
            cpasync16(&Bsm[nb + ldr * GROW + ldc],        bRow0 + k0);
            cpasync16(&Bsm[nb + (ldr + 64) * GROW + ldc], bRow1 + k0);
            cpasync_commit();
        }
        int cb = (t & 1) * 128 * GROW;
#pragma unroll
        for (int ks = 0; ks < 2; ks++) {
            int kk = ks * 8 + 2 * tig;
            uint32_t a[4][4], b[4][2];
#pragma unroll
            for (int i = 0; i < 4; i++) {
                int r = wm + i * 16 + gid;
                float2 av0 = *(const float2*)(&Asm[cb + r * GROW + kk]);
                float2 av1 = *(const float2*)(&Asm[cb + (r + 8) * GROW + kk]);
                a[i][0] = __float_as_uint(av0.x);
                a[i][1] = __float_as_uint(av1.x);
                a[i][2] = __float_as_uint(av0.y);
                a[i][3] = __float_as_uint(av1.y);
            }
#pragma unroll
            for (int j = 0; j < 4; j++) {
                int n = wn + j * 8 + gid;
                float2 bv2 = *(const float2*)(&Bsm[cb + n * GROW + kk]);
                b[j][0] = __float_as_uint(bv2.x);
                b[j][1] = __float_as_uint(bv2.y);
            }
#pragma unroll
            for (int i = 0; i < 4; i++)
#pragma unroll
                for (int j = 0; j < 4; j++)
                    mma_tf32(acc[i][j], a[i], b[j]);
        }
        __syncthreads();
    }

#pragma unroll
    for (int j = 0; j < 4; j++) {
        int col = n0 + wn + j * 8 + tig * 2;
        float2 bvv = *(const float2*)(bias_p + col);
#pragma unroll
        for (int i = 0; i < 4; i++) {
            int r = m0 + wm + i * 16 + gid;
            float2 v0 = make_float2(acc[i][j][0] + bvv.x, acc[i][j][1] + bvv.y);
            float2 v1 = make_float2(acc[i][j][2] + bvv.x, acc[i][j][3] + bvv.y);
            *(float2*)(C + (size_t)r * N + col)       = v0;
            *(float2*)(C + (size_t)(r + 8) * N + col) = v1;
        }
    }
}

// ==================== launch 3 (ncu-captured): persistent LSTM ====================
// 128 blocks x 256 thr, 1 block/SM. Block bx owns gate rows {gate nt, col j0+gid}.
// W_hh B-fragments in registers (standard k-slot order). h exchanged via transposed
// padded buffer g_hT[k*40 + b]; per step ONE mbarrier volley of 8 cp.async.bulk
// (160 KB, no per-granule LSU cost). smem copy = gmem layout; bank(40k + b) =
// 8*tig + gid (+8/+16) -> every a-frag LDS.32 is conflict-free.
// smem floats: hT 40960 | red 9216 | gs 1152 | mbar 16B
#define HT_BYTES (Hz * HTS * 4)
#define SMEM_LSTM (size_t)((Hz * HTS + 9216 + 1152) * sizeof(float) + 16)

__global__ __launch_bounds__(256)
void lstm_persistent(const float* __restrict__ Whh,
                     const float* __restrict__ fc_W,
                     const float* __restrict__ fc_b)
{
    extern __shared__ float sm[];
    float* hsm = sm;                           // [Hz*HTS] hT staging
    float* red = sm + Hz * HTS;                // [8][32][36]
    float* gs  = sm + Hz * HTS + 9216;         // [32][36]
    uint32_t smem_base = (uint32_t)__cvta_generic_to_shared(sm);
    uint32_t hsm_u32  = smem_base;
    uint32_t mbar_u32 = smem_base + (Hz * HTS + 9216 + 1152) * 4;

    int tid = threadIdx.x;
    int bx = blockIdx.x;
    int j0 = bx * 8;
    int lane = tid & 31;
    int w = tid >> 5;
    int gid = lane >> 2, tig = lane & 3;
    int bb = tid >> 3, jj = tid & 7;

    if (tid == 0) mbar_init(mbar_u32, 1);

    // ---- prologue A: W_hh B-fragments -> registers (standard order, RNA tf32) ----
    // Bf[s][nt] covers n = nt*8 + gid (global row nt*Hz + j0 + gid), k = 128w+8s+tig (+4)
    uint32_t Bf[16][4][2];
#pragma unroll
    for (int s = 0; s < 16; s++) {
#pragma unroll
        for (int nt = 0; nt < 4; nt++) {
            const float* wrow = Whh + (size_t)(nt * Hz + j0 + gid) * Hz + 128 * w + 8 * s + tig;
            Bf[s][nt][0] = __float_as_uint(round_tf32(wrow[0]));
            Bf[s][nt][1] = __float_as_uint(round_tf32(wrow[4]));
        }
    }

    // ---- prologue B: init h0/c0 for this block's columns (warp-coop dots) ----
    for (int oo = 0; oo < 64; oo++) {
        int o = w * 64 + oo;
        int b = o & 31, r = o >> 5;
        int grow = (r < 8) ? (j0 + r) : (Hz + j0 + (r - 8));
        const float4* wp = (const float4*)(fc_W + (size_t)grow * Fz);
        const float4* pp = (const float4*)(g_pooled + (size_t)b * Fz);
        float4 s4 = make_float4(0.f, 0.f, 0.f, 0.f);
        for (int f = lane; f < Fz / 4; f += 32) {
            float4 wv = wp[f];
            float4 pv = pp[f];
            s4.x += wv.x * pv.x; s4.y += wv.y * pv.y;
            s4.z += wv.z * pv.z; s4.w += wv.w * pv.w;
        }
        float v = (s4.x + s4.y) + (s4.z + s4.w);
#pragma unroll
        for (int off = 16; off; off >>= 1) v += __shfl_xor_sync(0xffffffffu, v, off);
        if (lane == 0) {
            v += fc_b[grow];
            if (r < 8) __stcg(&g_hT[0][(j0 + r) * HTS + b], v);
            else       gs[b * 36 + (r - 8)] = v;
        }
    }
    __syncthreads();
    float c_reg = gs[bb * 36 + jj];

    // grid barrier: all h0 visible
    __threadfence();
    __syncthreads();
    if (tid == 0) atomicExch(&g_flags[bx], 1);
    if (tid < NBLK) {
        while (((volatile int*)g_flags)[tid] < 1) __nanosleep(32);
    }
    __syncthreads();

    // ---- 128 timesteps ----
    for (int t = 0; t < Tz; t++) {
        const float* hT_in = g_hT[t & 1];
        float*       hT_out = g_hT[(t + 1) & 1];

        size_t gbase = ((size_t)bb * Tz + t) * (4 * Hz);
        float xi = __ldcs(&g_xW[gbase + 0 * Hz + j0 + jj]);
        float xf = __ldcs(&g_xW[gbase + 1 * Hz + j0 + jj]);
        float xg = __ldcs(&g_xW[gbase + 2 * Hz + j0 + jj]);
        float xo = __ldcs(&g_xW[gbase + 3 * Hz + j0 + jj]);

        // stage full hT in one mbarrier volley (8 bulk copies, 160 KB total)
        if (tid == 0) {
            mbar_expect_tx(mbar_u32, (uint32_t)HT_BYTES);
#pragma unroll
            for (int i = 0; i < 8; i++) {
                bulk_g2s(hsm_u32 + i * (HT_BYTES / 8),
                         hT_in + i * (Hz * HTS / 8),
                         HT_BYTES / 8, mbar_u32);
            }
        }
        mbar_wait_parity(mbar_u32, t & 1);

        float acc[2][4][4];
#pragma unroll
        for (int mt = 0; mt < 2; mt++)
#pragma unroll
            for (int nt = 0; nt < 4; nt++)
#pragma unroll
                for (int q = 0; q < 4; q++) acc[mt][nt][q] = 0.f;

#pragma unroll
        for (int s = 0; s < 16; s++) {
            int kb = 128 * w + 8 * s;
            const float* p0 = hsm + (kb + tig) * HTS;
            const float* p4 = hsm + (kb + tig + 4) * HTS;
            uint32_t a[2][4];
#pragma unroll
            for (int mt = 0; mt < 2; mt++) {
                int r0 = mt * 16 + gid;
                a[mt][0] = __float_as_uint(p0[r0]);
                a[mt][1] = __float_as_uint(p0[r0 + 8]);
                a[mt][2] = __float_as_uint(p4[r0]);
                a[mt][3] = __float_as_uint(p4[r0 + 8]);
            }
#pragma unroll
            for (int nt = 0; nt < 4; nt++) {
                mma_tf32(acc[0][nt], a[0], Bf[s][nt]);
                mma_tf32(acc[1][nt], a[1], Bf[s][nt]);
            }
        }

        // ---- cross-warp reduction ----
        __syncthreads();
#pragma unroll
        for (int mt = 0; mt < 2; mt++) {
#pragma unroll
            for (int nt = 0; nt < 4; nt++) {
                int row0 = mt * 16 + gid;
                int n = nt * 8 + 2 * tig;
                *(float2*)(red + (w * 32 + row0) * 36 + n) =
                    make_float2(acc[mt][nt][0], acc[mt][nt][1]);
                *(float2*)(red + (w * 32 + row0 + 8) * 36 + n) =
                    make_float2(acc[mt][nt][2], acc[mt][nt][3]);
            }
        }
        __syncthreads();
        {
            int b = tid >> 3, n4 = (tid & 7) * 4;
            float4 sum = make_float4(0.f, 0.f, 0.f, 0.f);
#pragma unroll
            for (int ww = 0; ww < 8; ww++) {
                float4 v = *(const float4*)(red + (ww * 32 + b) * 36 + n4);
                sum.x += v.x; sum.y += v.y; sum.z += v.z; sum.w += v.w;
            }
            *(float4*)(gs + b * 36 + n4) = sum;
        }
        __syncthreads();

        // ---- elementwise gate update ----
        float gi = gs[bb * 36 +  0 + jj] + xi;
        float gf = gs[bb * 36 +  8 + jj] + xf;
        float gg = gs[bb * 36 + 16 + jj] + xg;
        float go = gs[bb * 36 + 24 + jj] + xo;

        float cn = sigmoidf_(gf) * c_reg + sigmoidf_(gi) * tanhf(gg);
        float hn = sigmoidf_(go) * tanhf(cn);
        c_reg = cn;
        float hr = round_tf32(hn);
        __stcg(&hT_out[(j0 + jj) * HTS + bb], hr);
        g_hs[((size_t)bb * Tz + t) * Hz + j0 + jj] = hr;

        // ---- grid barrier ----
        __threadfence();
        __syncthreads();
        if (tid == 0) atomicExch(&g_flags[bx], t + 2);
        if (tid < NBLK) {
            while (((volatile int*)g_flags)[tid] < t + 2) __nanosleep(32);
        }
        __syncthreads();
    }
}

// ==================== launcher ====================
extern "C" void kernel_launch(void* const* d_in, const int* in_sizes, int n_in,
                              void* d_out, int out_size) {
    const float* features = (const float*)d_in[0];
    const int*   reports  = (const int*)d_in[1];
    const float* fc_W     = (const float*)d_in[2];
    const float* fc_b     = (const float*)d_in[3];
    const float* emb      = (const float*)d_in[4];
    const float* W_ih     = (const float*)d_in[5];
    const float* W_hh     = (const float*)d_in[6];
    const float* b_ih     = (const float*)d_in[7];
    const float* b_hh     = (const float*)d_in[8];
    const float* Wv       = (const float*)d_in[9];
    const float* bv       = (const float*)d_in[10];
    float* out = (float*)d_out;

    (void)in_sizes; (void)n_in; (void)out_size;

    cudaFuncSetAttribute(lstm_persistent,
                         cudaFuncAttributeMaxDynamicSharedMemorySize, (int)SMEM_LSTM);
    cudaFuncSetAttribute(gemm_tf32_kernel<0>,
                         cudaFuncAttributeMaxDynamicSharedMemorySize, (int)GEMM_SMEM);
    cudaFuncSetAttribute(gemm_tf32_kernel<1>,
                         cudaFuncAttributeMaxDynamicSharedMemorySize, (int)GEMM_SMEM);

    // launch 0: fused prep (pool + idx + bias + flags)
    prep_kernel<<<(Bz * Fz + 255) / 256, 256>>>(features, reports, b_ih, b_hh);

    // launch 1: fused tf32 rounding (Wv, emb, W_ih), float4
    {
        int n = (Vz * Hz + Vz * Ez + 4 * Hz * Ez) / 4;
        round_all_kernel<<<(n + 255) / 256, 256>>>((const float4*)Wv,
                                                   (const float4*)emb,
                                                   (const float4*)W_ih);
    }

    // launch 2: input GEMM  xW = emb[idx] @ W_ih^T + (b_ih + b_hh)
    gemm_tf32_kernel<0><<<dim3(Bz * Tz / 128, 4 * Hz / 128), 256, GEMM_SMEM>>>(nullptr, nullptr);

    // launch 3 (ncu-captured): persistent LSTM (init + 128 timesteps)
    lstm_persistent<<<NBLK, 256, SMEM_LSTM>>>(W_hh, fc_W, fc_b);

    // launch 4: projection  out = hs @ Wv^T + bv
    gemm_tf32_kernel<1><<<dim3(Bz * Tz / 128, Vz / 128), 256, GEMM_SMEM>>>(bv, out);
}

// round 11
// speedup vs baseline: 1.6349x; 1.0289x over previous
#include <cuda_runtime.h>
#include <math.h>
#include <stdint.h>

#define Bz 32
#define Tz 128
#define Vz 16000
#define Ez 512
#define Hz 1024
#define Fz 2048
#define NBLK 128
#define HTS 40                            // hT row stride in floats (conflict-free banks)

// -------- scratch (static device globals; no runtime allocation) --------
__device__ float g_pooled[Bz * Fz];
__device__ float g_hT[2][Hz * HTS];        // transposed h ping-pong: hT[k*HTS + b]
__device__ float g_xW[Bz * Tz * 4 * Hz];   // input-gate preactivations
__device__ float g_hs[Bz * Tz * Hz];       // hidden states (tf32-rounded)
__device__ float g_Wv[Vz * Hz];            // Wv tf32-rounded
__device__ float g_embt[Vz * Ez];          // emb tf32-rounded
__device__ float g_Wih[4 * Hz * Ez];       // W_ih tf32-rounded
__device__ float g_bihh[4 * Hz];           // b_ih + b_hh
__device__ int   g_idx[Bz * Tz];
__device__ int   g_flags[NBLK];

__device__ __forceinline__ float sigmoidf_(float x) {
    return 1.0f / (1.0f + expf(-x));
}
__device__ __forceinline__ float round_tf32(float x) {
    uint32_t u;
    asm("cvt.rna.tf32.f32 %0, %1;" : "=r"(u) : "f"(x));
    return __uint_as_float(u);
}
__device__ __forceinline__ void cpasync16(void* dst, const void* src) {
    uint32_t d = (uint32_t)__cvta_generic_to_shared(dst);
    asm volatile("cp.async.cg.shared.global [%0], [%1], 16;" :: "r"(d), "l"(src));
}
__device__ __forceinline__ void cpasync_commit() { asm volatile("cp.async.commit_group;"); }
__device__ __forceinline__ void cpasync_wait0()  { asm volatile("cp.async.wait_group 0;"); }

__device__ __forceinline__ void mma_tf32(float* c, const uint32_t* a, const uint32_t* b) {
    asm volatile(
        "mma.sync.aligned.m16n8k8.row.col.f32.tf32.tf32.f32 "
        "{%0,%1,%2,%3}, {%4,%5,%6,%7}, {%8,%9}, {%0,%1,%2,%3};"
        : "+f"(c[0]), "+f"(c[1]), "+f"(c[2]), "+f"(c[3])
        : "r"(a[0]), "r"(a[1]), "r"(a[2]), "r"(a[3]), "r"(b[0]), "r"(b[1]));
}

// ---- mbarrier + bulk-copy helpers ----
__device__ __forceinline__ void mbar_init(uint32_t a, uint32_t cnt) {
    asm volatile("mbarrier.init.shared.b64 [%0], %1;" :: "r"(a), "r"(cnt) : "memory");
}
__device__ __forceinline__ void mbar_expect_tx(uint32_t a, uint32_t bytes) {
    asm volatile("mbarrier.arrive.expect_tx.shared.b64 _, [%0], %1;"
                 :: "r"(a), "r"(bytes) : "memory");
}
__device__ __forceinline__ void mbar_wait_parity(uint32_t a, uint32_t parity) {
    uint32_t done;
    asm volatile(
        "{\n\t.reg .pred p;\n\t"
        "mbarrier.try_wait.parity.acquire.cta.shared::cta.b64 p, [%1], %2;\n\t"
        "selp.b32 %0, 1, 0, p;\n\t}"
        : "=r"(done) : "r"(a), "r"(parity) : "memory");
    if (!done) {
        asm volatile(
            "{\n\t.reg .pred P1;\n\t"
            "WL_%=:\n\t"
            "mbarrier.try_wait.parity.acquire.cta.shared::cta.b64 P1, [%0], %1, 0x989680;\n\t"
            "@P1 bra.uni WD_%=;\n\t"
            "bra.uni WL_%=;\n\t"
            "WD_%=:\n\t}"
            :: "r"(a), "r"(parity) : "memory");
    }
}
__device__ __forceinline__ void bulk_g2s(uint32_t dst_smem, const void* src,
                                         uint32_t bytes, uint32_t mbar) {
    asm volatile(
        "cp.async.bulk.shared::cta.global.mbarrier::complete_tx::bytes [%0], [%1], %2, [%3];"
        :: "r"(dst_smem), "l"(src), "r"(bytes), "r"(mbar) : "memory");
}

// ==================== launch 0: fused small prep ====================
__global__ void prep_kernel(const float* __restrict__ features,
                            const int* __restrict__ reports,
                            const float* __restrict__ b_ih,
                            const float* __restrict__ b_hh) {
    int n = blockIdx.x * blockDim.x + threadIdx.x;   // 65536 threads
    if (n < Bz * Fz) {
        const float* p = features + (size_t)n * 49;
        float s = 0.f;
#pragma unroll
        for (int i = 0; i < 49; i++) s += p[i];
        g_pooled[n] = s * (1.0f / 49.0f);
    }
    if (n < Bz * Tz) {
        int t = n & (Tz - 1);
        g_idx[n] = (t == 0) ? 1 : reports[n - 1];    // START_IDX = 1
    }
    if (n < 4 * Hz) g_bihh[n] = b_ih[n] + b_hh[n];
    if (n < NBLK) g_flags[n] = 0;
}

// ==================== launch 1: fused tf32 rounding (float4) ====================
__global__ void round_all_kernel(const float4* __restrict__ Wv,
                                 const float4* __restrict__ emb,
                                 const float4* __restrict__ Wih) {
    int i = blockIdx.x * blockDim.x + threadIdx.x;
    const int n1 = Vz * Hz / 4, n2 = Vz * Ez / 4, n3 = 4 * Hz * Ez / 4;
    float4 v;
    float4* dst;
    const float4* src;
    if (i < n1)            { src = Wv;  dst = (float4*)g_Wv;  }
    else if ((i -= n1) < n2) { src = emb; dst = (float4*)g_embt; }
    else if ((i -= n2) < n3) { src = Wih; dst = (float4*)g_Wih; }
    else return;
    v = src[i];
    v.x = round_tf32(v.x); v.y = round_tf32(v.y);
    v.z = round_tf32(v.z); v.w = round_tf32(v.w);
    dst[i] = v;
}

// ==================== TF32 tensor-core GEMM (launches 2 and 4) ====================
// BK=32, one __syncthreads per tile (prefetch issued after the sync -> safe),
// GROW=40 pad -> conflict-free frag LDS.64 per 16-lane phase.
#define GROW 40
#define GEMM_SMEM (size_t)(4 * 128 * GROW * sizeof(float))   // 2 mats x 2 bufs

template<int MODE>
__global__ __launch_bounds__(256)
void gemm_tf32_kernel(const float* __restrict__ bias, float* __restrict__ outp)
{
    extern __shared__ float psm[];
    float* Asm = psm;                       // [2][128*GROW]
    float* Bsm = psm + 2 * 128 * GROW;      // [2][128*GROW]

    constexpr int K = (MODE == 0) ? Ez : Hz;
    constexpr int N = (MODE == 0) ? 4 * Hz : Vz;
    const float* A  = (MODE == 0) ? g_embt : g_hs;
    const float* Bw = (MODE == 0) ? g_Wih : g_Wv;
    float* C        = (MODE == 0) ? g_xW : outp;
    const float* bias_p = (MODE == 0) ? g_bihh : bias;

    int tid = threadIdx.x;
    int m0 = blockIdx.x * 128;
    int n0 = blockIdx.y * 128;

    int wid = tid >> 5, lane = tid & 31;
    int wm = (wid >> 2) * 64;
    int wn = (wid & 3) * 32;
    int gid = lane >> 2, tig = lane & 3;

    float acc[4][4][4];
#pragma unroll
    for (int i = 0; i < 4; i++)
#pragma unroll
        for (int j = 0; j < 4; j++)
#pragma unroll
            for (int q = 0; q < 4; q++) acc[i][j][q] = 0.f;

    int ldr = tid >> 2;                 // 0..63
    int ldc = (tid & 3) * 4;            // 0,4,8,12

    const float* aRow0;
    const float* aRow1;
    if (MODE == 0) {
        aRow0 = A + (size_t)g_idx[m0 + ldr] * K;
        aRow1 = A + (size_t)g_idx[m0 + ldr + 64] * K;
    } else {
        aRow0 = A + (size_t)(m0 + ldr) * K;
        aRow1 = aRow0 + (size_t)64 * K;
    }
    const float* bRow0 = Bw + (size_t)(n0 + ldr) * K;
    const float* bRow1 = bRow0 + (size_t)64 * K;

    const int NT = K / 32;

    // prologue: tile 0 -> buf 0 (rows ldr/ldr+64, col chunks ldc/ldc+16)
    {
        cpasync16(&Asm[ldr * GROW + ldc],             aRow0 + ldc);
        cpasync16(&Asm[ldr * GROW + ldc + 16],        aRow0 + ldc + 16);
        cpasync16(&Asm[(ldr + 64) * GROW + ldc],      aRow1 + ldc);
        cpasync16(&Asm[(ldr + 64) * GROW + ldc + 16], aRow1 + ldc + 16);
        cpasync16(&Bsm[ldr * GROW + ldc],             bRow0 + ldc);
        cpasync16(&Bsm[ldr * GROW + ldc + 16],        bRow0 + ldc + 16);
        cpasync16(&Bsm[(ldr + 64) * GROW + ldc],      bRow1 + ldc);
        cpasync16(&Bsm[(ldr + 64) * GROW + ldc + 16], bRow1 + ldc + 16);
        cpasync_commit();
    }

    for (int t = 0; t < NT; t++) {
        cpasync_wait0();
        __syncthreads();                  // single barrier per tile
        if (t + 1 < NT) {
            int nb = ((t + 1) & 1) * 128 * GROW;
            int k0 = (t + 1) * 32 + ldc;
            cpasync16(&Asm[nb + ldr * GROW + ldc],             aRow0 + k0);
            cpasync16(&Asm[nb + ldr * GROW + ldc + 16],        aRow0 + k0 + 16);
            cpasync16(&Asm[nb + (ldr + 64) * GROW + ldc],      aRow1 + k0);
            cpasync16(&Asm[nb + (ldr + 64) * GROW + ldc + 16], aRow1 + k0 + 16);
            cpasync16(&Bsm[nb + ldr * GROW + ldc],             bRow0 + k0);
            cpasync16(&Bsm[nb + ldr * GROW + ldc + 16],        bRow0 + k0 + 16);
            cpasync16(&Bsm[nb + (ldr + 64) * GROW + ldc],      bRow1 + k0);
            cpasync16(&Bsm[nb + (ldr + 64) * GROW + ldc + 16], bRow1 + k0 + 16);
            cpasync_commit();
        }
        int cb = (t & 1) * 128 * GROW;
#pragma unroll
        for (int ks = 0; ks < 4; ks++) {
            int kk = ks * 8 + 2 * tig;
            uint32_t a[4][4], b[4][2];
#pragma unroll
            for (int i = 0; i < 4; i++) {
                int r = wm + i * 16 + gid;
                float2 av0 = *(const float2*)(&Asm[cb + r * GROW + kk]);
                float2 av1 = *(const float2*)(&Asm[cb + (r + 8) * GROW + kk]);
                a[i][0] = __float_as_uint(av0.x);
                a[i][1] = __float_as_uint(av1.x);
                a[i][2] = __float_as_uint(av0.y);
                a[i][3] = __float_as_uint(av1.y);
            }
#pragma unroll
            for (int j = 0; j < 4; j++) {
                int n = wn + j * 8 + gid;
                float2 bv2 = *(const float2*)(&Bsm[cb + n * GROW + kk]);
                b[j][0] = __float_as_uint(bv2.x);
                b[j][1] = __float_as_uint(bv2.y);
            }
#pragma unroll
            for (int i = 0; i < 4; i++)
#pragma unroll
                for (int j = 0; j < 4; j++)
                    mma_tf32(acc[i][j], a[i], b[j]);
        }
    }

#pragma unroll
    for (int j = 0; j < 4; j++) {
        int col = n0 + wn + j * 8 + tig * 2;
        float2 bvv = *(const float2*)(bias_p + col);
#pragma unroll
        for (int i = 0; i < 4; i++) {
            int r = m0 + wm + i * 16 + gid;
            float2 v0 = make_float2(acc[i][j][0] + bvv.x, acc[i][j][1] + bvv.y);
            float2 v1 = make_float2(acc[i][j][2] + bvv.x, acc[i][j][3] + bvv.y);
            *(float2*)(C + (size_t)r * N + col)       = v0;
            *(float2*)(C + (size_t)(r + 8) * N + col) = v1;
        }
    }
}

// ==================== launch 3 (ncu-captured): persistent LSTM ====================
// As R9 (bulk-copy hT exchange, W in registers), but the 160 KB volley is split
// into 8 chunks with 8 mbarriers: warp w waits ONLY for its own 20 KB k-slice
// (chunk w = k rows [128w, 128w+128)), so compute overlaps later chunks' arrival.
#define HT_BYTES (Hz * HTS * 4)
#define CHUNK_BYTES (HT_BYTES / 8)
#define SMEM_LSTM (size_t)((Hz * HTS + 9216 + 1152) * sizeof(float) + 64)

__global__ __launch_bounds__(256)
void lstm_persistent(const float* __restrict__ Whh,
                     const float* __restrict__ fc_W,
                     const float* __restrict__ fc_b)
{
    extern __shared__ float sm[];
    float* hsm = sm;                           // [Hz*HTS] hT staging
    float* red = sm + Hz * HTS;                // [8][32][36]
    float* gs  = sm + Hz * HTS + 9216;         // [32][36]
    uint32_t smem_base = (uint32_t)__cvta_generic_to_shared(sm);
    uint32_t hsm_u32  = smem_base;
    uint32_t mbar_u32 = smem_base + (Hz * HTS + 9216 + 1152) * 4;  // 8 mbarriers

    int tid = threadIdx.x;
    int bx = blockIdx.x;
    int j0 = bx * 8;
    int lane = tid & 31;
    int w = tid >> 5;
    int gid = lane >> 2, tig = lane & 3;
    int bb = tid >> 3, jj = tid & 7;

    if (tid < 8) mbar_init(mbar_u32 + 8 * tid, 1);

    // ---- prologue A: W_hh B-fragments -> registers (standard order, RNA tf32) ----
    uint32_t Bf[16][4][2];
#pragma unroll
    for (int s = 0; s < 16; s++) {
#pragma unroll
        for (int nt = 0; nt < 4; nt++) {
            const float* wrow = Whh + (size_t)(nt * Hz + j0 + gid) * Hz + 128 * w + 8 * s + tig;
            Bf[s][nt][0] = __float_as_uint(round_tf32(wrow[0]));
            Bf[s][nt][1] = __float_as_uint(round_tf32(wrow[4]));
        }
    }

    // ---- prologue B: init h0/c0 for this block's columns (warp-coop dots) ----
    for (int oo = 0; oo < 64; oo++) {
        int o = w * 64 + oo;
        int b = o & 31, r = o >> 5;
        int grow = (r < 8) ? (j0 + r) : (Hz + j0 + (r - 8));
        const float4* wp = (const float4*)(fc_W + (size_t)grow * Fz);
        const float4* pp = (const float4*)(g_pooled + (size_t)b * Fz);
        float4 s4 = make_float4(0.f, 0.f, 0.f, 0.f);
        for (int f = lane; f < Fz / 4; f += 32) {
            float4 wv = wp[f];
            float4 pv = pp[f];
            s4.x += wv.x * pv.x; s4.y += wv.y * pv.y;
            s4.z += wv.z * pv.z; s4.w += wv.w * pv.w;
        }
        float v = (s4.x + s4.y) + (s4.z + s4.w);
#pragma unroll
        for (int off = 16; off; off >>= 1) v += __shfl_xor_sync(0xffffffffu, v, off);
        if (lane == 0) {
            v += fc_b[grow];
            if (r < 8) __stcg(&g_hT[0][(j0 + r) * HTS + b], v);
            else       gs[b * 36 + (r - 8)] = v;
        }
    }
    __syncthreads();
    float c_reg = gs[bb * 36 + jj];

    // grid barrier: all h0 visible
    __threadfence();
    __syncthreads();
    if (tid == 0) atomicExch(&g_flags[bx], 1);
    if (tid < NBLK) {
        while (((volatile int*)g_flags)[tid] < 1) __nanosleep(32);
    }
    __syncthreads();

    // ---- 128 timesteps ----
    for (int t = 0; t < Tz; t++) {
        const float* hT_in = g_hT[t & 1];
        float*       hT_out = g_hT[(t + 1) & 1];

        size_t gbase = ((size_t)bb * Tz + t) * (4 * Hz);
        float xi = __ldcs(&g_xW[gbase + 0 * Hz + j0 + jj]);
        float xf = __ldcs(&g_xW[gbase + 1 * Hz + j0 + jj]);
        float xg = __ldcs(&g_xW[gbase + 2 * Hz + j0 + jj]);
        float xo = __ldcs(&g_xW[gbase + 3 * Hz + j0 + jj]);

        // stage hT: 8 chunked bulk copies, per-chunk mbarrier
        if (tid == 0) {
#pragma unroll
            for (int i = 0; i < 8; i++) {
                mbar_expect_tx(mbar_u32 + 8 * i, (uint32_t)CHUNK_BYTES);
                bulk_g2s(hsm_u32 + i * CHUNK_BYTES,
                         hT_in + i * (Hz * HTS / 8),
                         CHUNK_BYTES, mbar_u32 + 8 * i);
            }
        }
        // warp w waits only for its own k-slice (chunk w)
        mbar_wait_parity(mbar_u32 + 8 * w, t & 1);

        float acc[2][4][4];
#pragma unroll
        for (int mt = 0; mt < 2; mt++)
#pragma unroll
            for (int nt = 0; nt < 4; nt++)
#pragma unroll
                for (int q = 0; q < 4; q++) acc[mt][nt][q] = 0.f;

#pragma unroll
        for (int s = 0; s < 16; s++) {
            int kb = 128 * w + 8 * s;
            const float* p0 = hsm + (kb + tig) * HTS;
            const float* p4 = hsm + (kb + tig + 4) * HTS;
            uint32_t a[2][4];
#pragma unroll
            for (int mt = 0; mt < 2; mt++) {
                int r0 = mt * 16 + gid;
                a[mt][0] = __float_as_uint(p0[r0]);
                a[mt][1] = __float_as_uint(p0[r0 + 8]);
                a[mt][2] = __float_as_uint(p4[r0]);
                a[mt][3] = __float_as_uint(p4[r0 + 8]);
            }
#pragma unroll
            for (int nt = 0; nt < 4; nt++) {
                mma_tf32(acc[0][nt], a[0], Bf[s][nt]);
                mma_tf32(acc[1][nt], a[1], Bf[s][nt]);
            }
        }

        // ---- cross-warp reduction ----
        __syncthreads();
#pragma unroll
        for (int mt = 0; mt < 2; mt++) {
#pragma unroll
            for (int nt = 0; nt < 4; nt++) {
                int row0 = mt * 16 + gid;
                int n = nt * 8 + 2 * tig;
                *(float2*)(red + (w * 32 + row0) * 36 + n) =
                    make_float2(acc[mt][nt][0], acc[mt][nt][1]);
                *(float2*)(red + (w * 32 + row0 + 8) * 36 + n) =
                    make_float2(acc[mt][nt][2], acc[mt][nt][3]);
            }
        }
        __syncthreads();
        {
            int b = tid >> 3, n4 = (tid & 7) * 4;
            float4 sum = make_float4(0.f, 0.f, 0.f, 0.f);
#pragma unroll
            for (int ww = 0; ww < 8; ww++) {
                float4 v = *(const float4*)(red + (ww * 32 + b) * 36 + n4);
                sum.x += v.x; sum.y += v.y; sum.z += v.z; sum.w += v.w;
            }
            *(float4*)(gs + b * 36 + n4) = sum;
        }
        __syncthreads();

        // ---- elementwise gate update ----
        float gi = gs[bb * 36 +  0 + jj] + xi;
        float gf = gs[bb * 36 +  8 + jj] + xf;
        float gg = gs[bb * 36 + 16 + jj] + xg;
        float go = gs[bb * 36 + 24 + jj] + xo;

        float cn = sigmoidf_(gf) * c_reg + sigmoidf_(gi) * tanhf(gg);
        float hn = sigmoidf_(go) * tanhf(cn);
        c_reg = cn;
        float hr = round_tf32(hn);
        __stcg(&hT_out[(j0 + jj) * HTS + bb], hr);
        g_hs[((size_t)bb * Tz + t) * Hz + j0 + jj] = hr;

        // ---- grid barrier ----
        __threadfence();
        __syncthreads();
        if (tid == 0) atomicExch(&g_flags[bx], t + 2);
        if (tid < NBLK) {
            while (((volatile int*)g_flags)[tid] < t + 2) __nanosleep(32);
        }
        __syncthreads();
    }
}

// ==================== launcher ====================
extern "C" void kernel_launch(void* const* d_in, const int* in_sizes, int n_in,
                              void* d_out, int out_size) {
    const float* features = (const float*)d_in[0];
    const int*   reports  = (const int*)d_in[1];
    const float* fc_W     = (const float*)d_in[2];
    const float* fc_b     = (const float*)d_in[3];
    const float* emb      = (const float*)d_in[4];
    const float* W_ih     = (const float*)d_in[5];
    const float* W_hh     = (const float*)d_in[6];
    const float* b_ih     = (const float*)d_in[7];
    const float* b_hh     = (const float*)d_in[8];
    const float* Wv       = (const float*)d_in[9];
    const float* bv       = (const float*)d_in[10];
    float* out = (float*)d_out;

    (void)in_sizes; (void)n_in; (void)out_size;

    cudaFuncSetAttribute(lstm_persistent,
                         cudaFuncAttributeMaxDynamicSharedMemorySize, (int)SMEM_LSTM);
    cudaFuncSetAttribute(gemm_tf32_kernel<0>,
                         cudaFuncAttributeMaxDynamicSharedMemorySize, (int)GEMM_SMEM);
    cudaFuncSetAttribute(gemm_tf32_kernel<1>,
                         cudaFuncAttributeMaxDynamicSharedMemorySize, (int)GEMM_SMEM);

    // launch 0: fused prep (pool + idx + bias + flags)
    prep_kernel<<<(Bz * Fz + 255) / 256, 256>>>(features, reports, b_ih, b_hh);

    // launch 1: fused tf32 rounding (Wv, emb, W_ih), float4
    {
        int n = (Vz * Hz + Vz * Ez + 4 * Hz * Ez) / 4;
        round_all_kernel<<<(n + 255) / 256, 256>>>((const float4*)Wv,
                                                   (const float4*)emb,
                                                   (const float4*)W_ih);
    }

    // launch 2: input GEMM  xW = emb[idx] @ W_ih^T + (b_ih + b_hh)
    gemm_tf32_kernel<0><<<dim3(Bz * Tz / 128, 4 * Hz / 128), 256, GEMM_SMEM>>>(nullptr, nullptr);

    // launch 3 (ncu-captured): persistent LSTM (init + 128 timesteps)
    lstm_persistent<<<NBLK, 256, SMEM_LSTM>>>(W_hh, fc_W, fc_b);

    // launch 4: projection  out = hs @ Wv^T + bv
    gemm_tf32_kernel<1><<<dim3(Bz * Tz / 128, Vz / 128), 256, GEMM_SMEM>>>(bv, out);
}

// round 12
// speedup vs baseline: 2.2605x; 1.3826x over previous
#include <cuda_runtime.h>
#include <cuda_fp16.h>
#include <math.h>
#include <stdint.h>

#define Bz 32
#define Tz 128
#define Vz 16000
#define Ez 512
#define Hz 1024
#define Fz 2048
#define NBLK 128
#define HPS 40                             // half2-row stride for hTp (conflict-free)

// -------- scratch (static device globals; no runtime allocation) --------
__device__ float   g_pooled[Bz * Fz];
__device__ __half2 g_hTp[2][(Hz / 2) * HPS];   // transposed h ping-pong: [kp][b] fp16 pairs
__device__ float   g_xW[Bz * Tz * 4 * Hz];     // input-gate preactivations (fp32)
__device__ __half  g_hs16[Bz * Tz * Hz];       // hidden states fp16 (proj A)
__device__ __half  g_Wv16[Vz * Hz];
__device__ __half  g_embt16[Vz * Ez];
__device__ __half  g_Wih16[4 * Hz * Ez];
__device__ float   g_bihh[4 * Hz];             // b_ih + b_hh
__device__ int     g_idx[Bz * Tz];
__device__ int     g_flags[NBLK];

__device__ __forceinline__ float sigmoidf_(float x) {
    return 1.0f / (1.0f + expf(-x));
}
__device__ __forceinline__ uint32_t pack_h2(float x, float y) {
    __half2 h = __float22half2_rn(make_float2(x, y));
    return *reinterpret_cast<uint32_t*>(&h);
}
__device__ __forceinline__ void cpasync16(void* dst, const void* src) {
    uint32_t d = (uint32_t)__cvta_generic_to_shared(dst);
    asm volatile("cp.async.cg.shared.global [%0], [%1], 16;" :: "r"(d), "l"(src));
}
__device__ __forceinline__ void cpasync_commit() { asm volatile("cp.async.commit_group;"); }
__device__ __forceinline__ void cpasync_wait0()  { asm volatile("cp.async.wait_group 0;"); }

__device__ __forceinline__ void mma_f16(float* c, const uint32_t* a, const uint32_t* b) {
    asm volatile(
        "mma.sync.aligned.m16n8k16.row.col.f32.f16.f16.f32 "
        "{%0,%1,%2,%3}, {%4,%5,%6,%7}, {%8,%9}, {%0,%1,%2,%3};"
        : "+f"(c[0]), "+f"(c[1]), "+f"(c[2]), "+f"(c[3])
        : "r"(a[0]), "r"(a[1]), "r"(a[2]), "r"(a[3]), "r"(b[0]), "r"(b[1]));
}

// ---- mbarrier + bulk-copy helpers ----
__device__ __forceinline__ void mbar_init(uint32_t a, uint32_t cnt) {
    asm volatile("mbarrier.init.shared.b64 [%0], %1;" :: "r"(a), "r"(cnt) : "memory");
}
__device__ __forceinline__ void mbar_expect_tx(uint32_t a, uint32_t bytes) {
    asm volatile("mbarrier.arrive.expect_tx.shared.b64 _, [%0], %1;"
                 :: "r"(a), "r"(bytes) : "memory");
}
__device__ __forceinline__ void mbar_wait_parity(uint32_t a, uint32_t parity) {
    uint32_t done;
    asm volatile(
        "{\n\t.reg .pred p;\n\t"
        "mbarrier.try_wait.parity.acquire.cta.shared::cta.b64 p, [%1], %2;\n\t"
        "selp.b32 %0, 1, 0, p;\n\t}"
        : "=r"(done) : "r"(a), "r"(parity) : "memory");
    if (!done) {
        asm volatile(
            "{\n\t.reg .pred P1;\n\t"
            "WL_%=:\n\t"
            "mbarrier.try_wait.parity.acquire.cta.shared::cta.b64 P1, [%0], %1, 0x989680;\n\t"
            "@P1 bra.uni WD_%=;\n\t"
            "bra.uni WL_%=;\n\t"
            "WD_%=:\n\t}"
            :: "r"(a), "r"(parity) : "memory");
    }
}
__device__ __forceinline__ void bulk_g2s(uint32_t dst_smem, const void* src,
                                         uint32_t bytes, uint32_t mbar) {
    asm volatile(
        "cp.async.bulk.shared::cta.global.mbarrier::complete_tx::bytes [%0], [%1], %2, [%3];"
        :: "r"(dst_smem), "l"(src), "r"(bytes), "r"(mbar) : "memory");
}

// ==================== launch 0: fused small prep ====================
__global__ void prep_kernel(const float* __restrict__ features,
                            const int* __restrict__ reports,
                            const float* __restrict__ b_ih,
                            const float* __restrict__ b_hh) {
    int n = blockIdx.x * blockDim.x + threadIdx.x;   // 65536 threads
    if (n < Bz * Fz) {
        const float* p = features + (size_t)n * 49;
        float s = 0.f;
#pragma unroll
        for (int i = 0; i < 49; i++) s += p[i];
        g_pooled[n] = s * (1.0f / 49.0f);
    }
    if (n < Bz * Tz) {
        int t = n & (Tz - 1);
        g_idx[n] = (t == 0) ? 1 : reports[n - 1];    // START_IDX = 1
    }
    if (n < 4 * Hz) g_bihh[n] = b_ih[n] + b_hh[n];
    if (n < NBLK) g_flags[n] = 0;
}

// ==================== launch 1: fp32 -> fp16 conversion (float4 -> 4 halfs) ====================
__global__ void round_all_kernel(const float4* __restrict__ Wv,
                                 const float4* __restrict__ emb,
                                 const float4* __restrict__ Wih) {
    int i = blockIdx.x * blockDim.x + threadIdx.x;
    const int n1 = Vz * Hz / 4, n2 = Vz * Ez / 4, n3 = 4 * Hz * Ez / 4;
    const float4* src;
    __half* dst;
    if (i < n1)              { src = Wv;  dst = g_Wv16;  }
    else if ((i -= n1) < n2) { src = emb; dst = g_embt16; }
    else if ((i -= n2) < n3) { src = Wih; dst = g_Wih16; }
    else return;
    float4 v = src[i];
    uint2 pk = make_uint2(pack_h2(v.x, v.y), pack_h2(v.z, v.w));
    *(uint2*)(dst + 4 * (size_t)i) = pk;
}

// ==================== fp16 tensor-core GEMM (launches 2 and 4) ====================
// MODE 0: g_xW = emb16[g_idx rows] @ Wih16^T + g_bihh   (M=4096, N=4096, K=512)
// MODE 1: out  = hs16 @ Wv16^T + bias                   (M=4096, N=16000, K=1024)
// BK=32 halfs (64B/row), row stride GROWH=40 halfs -> frag banks 20*gid+tig: conflict-free.
#define GROWH 40
#define GEMM_SMEM (size_t)(4 * 128 * GROWH * sizeof(__half))   // 40 KB

template<int MODE>
__global__ __launch_bounds__(256)
void gemm_f16_kernel(const float* __restrict__ bias, float* __restrict__ outp)
{
    extern __shared__ __half gsm[];
    __half* Asm = gsm;                        // [2][128*GROWH]
    __half* Bsm = gsm + 2 * 128 * GROWH;      // [2][128*GROWH]

    constexpr int K = (MODE == 0) ? Ez : Hz;
    constexpr int N = (MODE == 0) ? 4 * Hz : Vz;
    const __half* A  = (MODE == 0) ? g_embt16 : g_hs16;
    const __half* Bw = (MODE == 0) ? g_Wih16 : g_Wv16;
    float* C         = (MODE == 0) ? g_xW : outp;
    const float* bias_p = (MODE == 0) ? g_bihh : bias;

    int tid = threadIdx.x;
    int m0 = blockIdx.x * 128;
    int n0 = blockIdx.y * 128;

    int wid = tid >> 5, lane = tid & 31;
    int wm = (wid >> 2) * 64;
    int wn = (wid & 3) * 32;
    int gid = lane >> 2, tig = lane & 3;

    float acc[4][4][4];
#pragma unroll
    for (int i = 0; i < 4; i++)
#pragma unroll
        for (int j = 0; j < 4; j++)
#pragma unroll
            for (int q = 0; q < 4; q++) acc[i][j][q] = 0.f;

    int ldr = tid >> 2;                 // 0..63
    int ldcH = (tid & 3) * 8;           // half offset: 0,8,16,24 (16B chunks)

    const __half* aRow0;
    const __half* aRow1;
    if (MODE == 0) {
        aRow0 = A + (size_t)g_idx[m0 + ldr] * K;
        aRow1 = A + (size_t)g_idx[m0 + ldr + 64] * K;
    } else {
        aRow0 = A + (size_t)(m0 + ldr) * K;
        aRow1 = aRow0 + (size_t)64 * K;
    }
    const __half* bRow0 = Bw + (size_t)(n0 + ldr) * K;
    const __half* bRow1 = bRow0 + (size_t)64 * K;

    const int NT = K / 32;

    cpasync16(&Asm[ldr * GROWH + ldcH],        aRow0 + ldcH);
    cpasync16(&Asm[(ldr + 64) * GROWH + ldcH], aRow1 + ldcH);
    cpasync16(&Bsm[ldr * GROWH + ldcH],        bRow0 + ldcH);
    cpasync16(&Bsm[(ldr + 64) * GROWH + ldcH], bRow1 + ldcH);
    cpasync_commit();

    for (int t = 0; t < NT; t++) {
        cpasync_wait0();
        __syncthreads();                  // single barrier per tile (prefetch after)
        if (t + 1 < NT) {
            int nb = ((t + 1) & 1) * 128 * GROWH;
            int k0 = (t + 1) * 32 + ldcH;
            cpasync16(&Asm[nb + ldr * GROWH + ldcH],        aRow0 + k0);
            cpasync16(&Asm[nb + (ldr + 64) * GROWH + ldcH], aRow1 + k0);
            cpasync16(&Bsm[nb + ldr * GROWH + ldcH],        bRow0 + k0);
            cpasync16(&Bsm[nb + (ldr + 64) * GROWH + ldcH], bRow1 + k0);
            cpasync_commit();
        }
        int cb = (t & 1) * 128 * GROWH;
#pragma unroll
        for (int ks = 0; ks < 2; ks++) {
            int kb = ks * 16;
            uint32_t a[4][4], b[4][2];
#pragma unroll
            for (int i = 0; i < 4; i++) {
                int r = wm + i * 16 + gid;
                a[i][0] = *(const uint32_t*)(&Asm[cb + r * GROWH + kb + 2 * tig]);
                a[i][1] = *(const uint32_t*)(&Asm[cb + (r + 8) * GROWH + kb + 2 * tig]);
                a[i][2] = *(const uint32_t*)(&Asm[cb + r * GROWH + kb + 8 + 2 * tig]);
                a[i][3] = *(const uint32_t*)(&Asm[cb + (r + 8) * GROWH + kb + 8 + 2 * tig]);
            }
#pragma unroll
            for (int j = 0; j < 4; j++) {
                int n = wn + j * 8 + gid;
                b[j][0] = *(const uint32_t*)(&Bsm[cb + n * GROWH + kb + 2 * tig]);
                b[j][1] = *(const uint32_t*)(&Bsm[cb + n * GROWH + kb + 8 + 2 * tig]);
            }
#pragma unroll
            for (int i = 0; i < 4; i++)
#pragma unroll
                for (int j = 0; j < 4; j++)
                    mma_f16(acc[i][j], a[i], b[j]);
        }
    }

#pragma unroll
    for (int j = 0; j < 4; j++) {
        int col = n0 + wn + j * 8 + tig * 2;
        float2 bvv = *(const float2*)(bias_p + col);
#pragma unroll
        for (int i = 0; i < 4; i++) {
            int r = m0 + wm + i * 16 + gid;
            float2 v0 = make_float2(acc[i][j][0] + bvv.x, acc[i][j][1] + bvv.y);
            float2 v1 = make_float2(acc[i][j][2] + bvv.x, acc[i][j][3] + bvv.y);
            *(float2*)(C + (size_t)r * N + col)       = v0;
            *(float2*)(C + (size_t)(r + 8) * N + col) = v1;
        }
    }
}

// ==================== launch 3 (ncu-captured): persistent LSTM (fp16 mma) ====================
// 128 blocks x 256 thr, 1 block/SM. Block bx owns h cols [8bx, 8bx+8) = 32 gate-rows.
// W_hh B-frags in regs as fp16 pairs (64 u32/thread). h exchanged as half2[kp][b]
// (stride HPS=40 half2 -> a-frag banks 8*tig+gid: conflict-free). 80 KB bulk volley
// per step, 8 chunks / 8 mbarriers; warp w waits only its own k-slice.
#define HT_BYTES ((Hz / 2) * HPS * 4)          // 81920
#define CHUNK_BYTES (HT_BYTES / 8)             // 10240
#define SMEM_LSTM (size_t)(HT_BYTES + (9216 + 1152) * 4 + 64)   // 123456

__global__ __launch_bounds__(256)
void lstm_persistent(const float* __restrict__ Whh,
                     const float* __restrict__ fc_W,
                     const float* __restrict__ fc_b)
{
    extern __shared__ char smraw[];
    __half2* hsm2 = (__half2*)smraw;                       // [(Hz/2)*HPS]
    float* red = (float*)(smraw + HT_BYTES);               // [8][32][36]
    float* gs  = (float*)(smraw + HT_BYTES + 9216 * 4);    // [32][36]
    uint32_t smem_base = (uint32_t)__cvta_generic_to_shared(smraw);
    uint32_t hsm_u32  = smem_base;
    uint32_t mbar_u32 = smem_base + HT_BYTES + (9216 + 1152) * 4;  // 8 mbarriers

    int tid = threadIdx.x;
    int bx = blockIdx.x;
    int j0 = bx * 8;
    int lane = tid & 31;
    int w = tid >> 5;
    int gid = lane >> 2, tig = lane & 3;
    int bb = tid >> 3, jj = tid & 7;

    if (tid < 8) mbar_init(mbar_u32 + 8 * tid, 1);

    // ---- prologue A: W_hh B-fragments -> registers (fp16 pairs) ----
    // Bf[s][nt]: n-row = nt*Hz + j0 + gid, k = 128w + 16s + 2tig (b0: k,k+1; b1: +8)
    uint32_t Bf[8][4][2];
#pragma unroll
    for (int s = 0; s < 8; s++) {
#pragma unroll
        for (int nt = 0; nt < 4; nt++) {
            const float* wrow = Whh + (size_t)(nt * Hz + j0 + gid) * Hz + 128 * w + 16 * s + 2 * tig;
            float2 w0 = *(const float2*)(wrow);
            float2 w1 = *(const float2*)(wrow + 8);
            Bf[s][nt][0] = pack_h2(w0.x, w0.y);
            Bf[s][nt][1] = pack_h2(w1.x, w1.y);
        }
    }

    // ---- prologue B: init h0/c0 for this block's columns (warp-coop dots) ----
    for (int oo = 0; oo < 64; oo++) {
        int o = w * 64 + oo;
        int b = o & 31, r = o >> 5;
        int grow = (r < 8) ? (j0 + r) : (Hz + j0 + (r - 8));
        const float4* wp = (const float4*)(fc_W + (size_t)grow * Fz);
        const float4* pp = (const float4*)(g_pooled + (size_t)b * Fz);
        float4 s4 = make_float4(0.f, 0.f, 0.f, 0.f);
        for (int f = lane; f < Fz / 4; f += 32) {
            float4 wv = wp[f];
            float4 pv = pp[f];
            s4.x += wv.x * pv.x; s4.y += wv.y * pv.y;
            s4.z += wv.z * pv.z; s4.w += wv.w * pv.w;
        }
        float v = (s4.x + s4.y) + (s4.z + s4.w);
#pragma unroll
        for (int off = 16; off; off >>= 1) v += __shfl_xor_sync(0xffffffffu, v, off);
        if (lane == 0) {
            v += fc_b[grow];
            if (r < 8) {
                int k = j0 + r;
                __half* hp = (__half*)&g_hTp[0][(k >> 1) * HPS + b];
                hp[k & 1] = __float2half_rn(v);
            } else {
                gs[b * 36 + (r - 8)] = v;
            }
        }
    }
    __syncthreads();
    float c_reg = gs[bb * 36 + jj];

    // grid barrier: all h0 visible
    __threadfence();
    __syncthreads();
    if (tid == 0) atomicExch(&g_flags[bx], 1);
    if (tid < NBLK) {
        while (((volatile int*)g_flags)[tid] < 1) __nanosleep(32);
    }
    __syncthreads();

    // ---- 128 timesteps ----
    for (int t = 0; t < Tz; t++) {
        const __half2* hT_in = g_hTp[t & 1];
        __half2*       hT_out = g_hTp[(t + 1) & 1];

        size_t gbase = ((size_t)bb * Tz + t) * (4 * Hz);
        float xi = __ldcs(&g_xW[gbase + 0 * Hz + j0 + jj]);
        float xf = __ldcs(&g_xW[gbase + 1 * Hz + j0 + jj]);
        float xg = __ldcs(&g_xW[gbase + 2 * Hz + j0 + jj]);
        float xo = __ldcs(&g_xW[gbase + 3 * Hz + j0 + jj]);

        // stage hTp: 8 chunked bulk copies (10 KB each), per-chunk mbarrier
        if (tid == 0) {
#pragma unroll
            for (int i = 0; i < 8; i++) {
                mbar_expect_tx(mbar_u32 + 8 * i, (uint32_t)CHUNK_BYTES);
                bulk_g2s(hsm_u32 + i * CHUNK_BYTES,
                         (const char*)hT_in + i * CHUNK_BYTES,
                         CHUNK_BYTES, mbar_u32 + 8 * i);
            }
        }
        // warp w waits only for its own k-slice (chunk w: kp in [64w, 64w+64))
        mbar_wait_parity(mbar_u32 + 8 * w, t & 1);

        float acc[2][4][4];
#pragma unroll
        for (int mt = 0; mt < 2; mt++)
#pragma unroll
            for (int nt = 0; nt < 4; nt++)
#pragma unroll
                for (int q = 0; q < 4; q++) acc[mt][nt][q] = 0.f;

#pragma unroll
        for (int s = 0; s < 8; s++) {
            int kpb = 64 * w + 8 * s;
            uint32_t a[2][4];
#pragma unroll
            for (int mt = 0; mt < 2; mt++) {
                int m = mt * 16 + gid;
                a[mt][0] = *(const uint32_t*)(&hsm2[(kpb + tig) * HPS + m]);
                a[mt][1] = *(const uint32_t*)(&hsm2[(kpb + tig) * HPS + m + 8]);
                a[mt][2] = *(const uint32_t*)(&hsm2[(kpb + tig + 4) * HPS + m]);
                a[mt][3] = *(const uint32_t*)(&hsm2[(kpb + tig + 4) * HPS + m + 8]);
            }
#pragma unroll
            for (int nt = 0; nt < 4; nt++) {
                mma_f16(acc[0][nt], a[0], Bf[s][nt]);
                mma_f16(acc[1][nt], a[1], Bf[s][nt]);
            }
        }

        // ---- cross-warp reduction ----
        __syncthreads();
#pragma unroll
        for (int mt = 0; mt < 2; mt++) {
#pragma unroll
            for (int nt = 0; nt < 4; nt++) {
                int row0 = mt * 16 + gid;
                int n = nt * 8 + 2 * tig;
                *(float2*)(red + (w * 32 + row0) * 36 + n) =
                    make_float2(acc[mt][nt][0], acc[mt][nt][1]);
                *(float2*)(red + (w * 32 + row0 + 8) * 36 + n) =
                    make_float2(acc[mt][nt][2], acc[mt][nt][3]);
            }
        }
        __syncthreads();
        {
            int b = tid >> 3, n4 = (tid & 7) * 4;
            float4 sum = make_float4(0.f, 0.f, 0.f, 0.f);
#pragma unroll
            for (int ww = 0; ww < 8; ww++) {
                float4 v = *(const float4*)(red + (ww * 32 + b) * 36 + n4);
                sum.x += v.x; sum.y += v.y; sum.z += v.z; sum.w += v.w;
            }
            *(float4*)(gs + b * 36 + n4) = sum;
        }
        __syncthreads();

        // ---- elementwise gate update ----
        float gi = gs[bb * 36 +  0 + jj] + xi;
        float gf = gs[bb * 36 +  8 + jj] + xf;
        float gg = gs[bb * 36 + 16 + jj] + xg;
        float go = gs[bb * 36 + 24 + jj] + xo;

        float cn = sigmoidf_(gf) * c_reg + sigmoidf_(gi) * tanhf(gg);
        float hn = sigmoidf_(go) * tanhf(cn);
        c_reg = cn;
        __half hr16 = __float2half_rn(hn);
        {
            int k = j0 + jj;
            __half* hp = (__half*)&hT_out[(k >> 1) * HPS + bb];
            hp[k & 1] = hr16;
            g_hs16[((size_t)bb * Tz + t) * Hz + k] = hr16;
        }

        // ---- grid barrier ----
        __threadfence();
        __syncthreads();
        if (tid == 0) atomicExch(&g_flags[bx], t + 2);
        if (tid < NBLK) {
            while (((volatile int*)g_flags)[tid] < t + 2) __nanosleep(32);
        }
        __syncthreads();
    }
}

// ==================== launcher ====================
extern "C" void kernel_launch(void* const* d_in, const int* in_sizes, int n_in,
                              void* d_out, int out_size) {
    const float* features = (const float*)d_in[0];
    const int*   reports  = (const int*)d_in[1];
    const float* fc_W     = (const float*)d_in[2];
    const float* fc_b     = (const float*)d_in[3];
    const float* emb      = (const float*)d_in[4];
    const float* W_ih     = (const float*)d_in[5];
    const float* W_hh     = (const float*)d_in[6];
    const float* b_ih     = (const float*)d_in[7];
    const float* b_hh     = (const float*)d_in[8];
    const float* Wv       = (const float*)d_in[9];
    const float* bv       = (const float*)d_in[10];
    float* out = (float*)d_out;

    (void)in_sizes; (void)n_in; (void)out_size;

    cudaFuncSetAttribute(lstm_persistent,
                         cudaFuncAttributeMaxDynamicSharedMemorySize, (int)SMEM_LSTM);
    cudaFuncSetAttribute(gemm_f16_kernel<0>,
                         cudaFuncAttributeMaxDynamicSharedMemorySize, (int)GEMM_SMEM);
    cudaFuncSetAttribute(gemm_f16_kernel<1>,
                         cudaFuncAttributeMaxDynamicSharedMemorySize, (int)GEMM_SMEM);

    // launch 0: fused prep (pool + idx + bias + flags)
    prep_kernel<<<(Bz * Fz + 255) / 256, 256>>>(features, reports, b_ih, b_hh);

    // launch 1: fp32 -> fp16 conversion (Wv, emb, W_ih)
    {
        int n = (Vz * Hz + Vz * Ez + 4 * Hz * Ez) / 4;
        round_all_kernel<<<(n + 255) / 256, 256>>>((const float4*)Wv,
                                                   (const float4*)emb,
                                                   (const float4*)W_ih);
    }

    // launch 2: input GEMM  xW = emb[idx] @ W_ih^T + (b_ih + b_hh)
    gemm_f16_kernel<0><<<dim3(Bz * Tz / 128, 4 * Hz / 128), 256, GEMM_SMEM>>>(nullptr, nullptr);

    // launch 3 (ncu-captured): persistent LSTM (init + 128 timesteps)
    lstm_persistent<<<NBLK, 256, SMEM_LSTM>>>(W_hh, fc_W, fc_b);

    // launch 4: projection  out = hs @ Wv^T + bv
    gemm_f16_kernel<1><<<dim3(Bz * Tz / 128, Vz / 128), 256, GEMM_SMEM>>>(bv, out);
}

// round 13
// speedup vs baseline: 2.2776x; 1.0076x over previous
#include <cuda_runtime.h>
#include <cuda_fp16.h>
#include <math.h>
#include <stdint.h>

#define Bz 32
#define Tz 128
#define Vz 16000
#define Ez 512
#define Hz 1024
#define Fz 2048
#define NBLK 128
#define HPS 40                             // half2-row stride for hTp

// -------- scratch (static device globals; no runtime allocation) --------
__device__ float   g_pooled[Bz * Fz];
__device__ __half2 g_hTp[2][(Hz / 2) * HPS];   // transposed h ping-pong: [kp][b] fp16 pairs
__device__ float   g_xW[Bz * Tz * 4 * Hz];     // input-gate preactivations (fp32)
__device__ __half  g_hs16[Bz * Tz * Hz];       // hidden states fp16 (proj A)
__device__ __half  g_Wv16[Vz * Hz];
__device__ __half  g_embt16[Vz * Ez];
__device__ __half  g_Wih16[4 * Hz * Ez];
__device__ float   g_bihh[4 * Hz];             // b_ih + b_hh
__device__ int     g_idx[Bz * Tz];
__device__ int     g_flags[NBLK];

__device__ __forceinline__ float sigmoidf_(float x) {
    return 1.0f / (1.0f + expf(-x));
}
__device__ __forceinline__ uint32_t pack_h2(float x, float y) {
    __half2 h = __float22half2_rn(make_float2(x, y));
    return *reinterpret_cast<uint32_t*>(&h);
}
__device__ __forceinline__ void cpasync16(void* dst, const void* src) {
    uint32_t d = (uint32_t)__cvta_generic_to_shared(dst);
    asm volatile("cp.async.cg.shared.global [%0], [%1], 16;" :: "r"(d), "l"(src));
}
__device__ __forceinline__ void cpasync_commit() { asm volatile("cp.async.commit_group;"); }
__device__ __forceinline__ void cpasync_wait0()  { asm volatile("cp.async.wait_group 0;"); }

__device__ __forceinline__ void mma_f16(float* c, const uint32_t* a, const uint32_t* b) {
    asm volatile(
        "mma.sync.aligned.m16n8k16.row.col.f32.f16.f16.f32 "
        "{%0,%1,%2,%3}, {%4,%5,%6,%7}, {%8,%9}, {%0,%1,%2,%3};"
        : "+f"(c[0]), "+f"(c[1]), "+f"(c[2]), "+f"(c[3])
        : "r"(a[0]), "r"(a[1]), "r"(a[2]), "r"(a[3]), "r"(b[0]), "r"(b[1]));
}
__device__ __forceinline__ void ldsm_x4(uint32_t& r0, uint32_t& r1, uint32_t& r2, uint32_t& r3,
                                        uint32_t addr) {
    asm volatile("ldmatrix.sync.aligned.m8n8.x4.shared.b16 {%0,%1,%2,%3}, [%4];"
                 : "=r"(r0), "=r"(r1), "=r"(r2), "=r"(r3) : "r"(addr));
}

// ==================== launch 0: fused small prep ====================
__global__ void prep_kernel(const float* __restrict__ features,
                            const int* __restrict__ reports,
                            const float* __restrict__ b_ih,
                            const float* __restrict__ b_hh) {
    int n = blockIdx.x * blockDim.x + threadIdx.x;   // 65536 threads
    if (n < Bz * Fz) {
        const float* p = features + (size_t)n * 49;
        float s = 0.f;
#pragma unroll
        for (int i = 0; i < 49; i++) s += p[i];
        g_pooled[n] = s * (1.0f / 49.0f);
    }
    if (n < Bz * Tz) {
        int t = n & (Tz - 1);
        g_idx[n] = (t == 0) ? 1 : reports[n - 1];    // START_IDX = 1
    }
    if (n < 4 * Hz) g_bihh[n] = b_ih[n] + b_hh[n];
    if (n < NBLK) g_flags[n] = 0;
}

// ==================== launch 1: fp32 -> fp16 conversion ====================
__global__ void round_all_kernel(const float4* __restrict__ Wv,
                                 const float4* __restrict__ emb,
                                 const float4* __restrict__ Wih) {
    int i = blockIdx.x * blockDim.x + threadIdx.x;
    const int n1 = Vz * Hz / 4, n2 = Vz * Ez / 4, n3 = 4 * Hz * Ez / 4;
    const float4* src;
    __half* dst;
    if (i < n1)              { src = Wv;  dst = g_Wv16;  }
    else if ((i -= n1) < n2) { src = emb; dst = g_embt16; }
    else if ((i -= n2) < n3) { src = Wih; dst = g_Wih16; }
    else return;
    float4 v = src[i];
    uint2 pk = make_uint2(pack_h2(v.x, v.y), pack_h2(v.z, v.w));
    *(uint2*)(dst + 4 * (size_t)i) = pk;
}

// ==================== fp16 tensor-core GEMM (launches 2 and 4), ldmatrix frags ====
#define GROWH 40
#define GEMM_SMEM (size_t)(4 * 128 * GROWH * sizeof(__half))   // 40 KB

template<int MODE>
__global__ __launch_bounds__(256)
void gemm_f16_kernel(const float* __restrict__ bias, float* __restrict__ outp)
{
    extern __shared__ __half gsm[];
    __half* Asm = gsm;                        // [2][128*GROWH]
    __half* Bsm = gsm + 2 * 128 * GROWH;      // [2][128*GROWH]

    constexpr int K = (MODE == 0) ? Ez : Hz;
    constexpr int N = (MODE == 0) ? 4 * Hz : Vz;
    const __half* A  = (MODE == 0) ? g_embt16 : g_hs16;
    const __half* Bw = (MODE == 0) ? g_Wih16 : g_Wv16;
    float* C         = (MODE == 0) ? g_xW : outp;
    const float* bias_p = (MODE == 0) ? g_bihh : bias;

    int tid = threadIdx.x;
    int m0 = blockIdx.x * 128;
    int n0 = blockIdx.y * 128;

    int wid = tid >> 5, lane = tid & 31;
    int wm = (wid >> 2) * 64;
    int wn = (wid & 3) * 32;
    int gid = lane >> 2, tig = lane & 3;

    // ldmatrix per-lane row/col offsets
    int mat = lane >> 3, lr = lane & 7;
    int rowA = wm + (mat & 1) * 8 + lr;       // + i*16
    int kA   = (mat >> 1) * 8;
    int rowB = wn + (mat >> 1) * 8 + lr;      // + p*16
    int kB   = (mat & 1) * 8;
    uint32_t asm_u32 = (uint32_t)__cvta_generic_to_shared(Asm);
    uint32_t bsm_u32 = (uint32_t)__cvta_generic_to_shared(Bsm);

    float acc[4][4][4];
#pragma unroll
    for (int i = 0; i < 4; i++)
#pragma unroll
        for (int j = 0; j < 4; j++)
#pragma unroll
            for (int q = 0; q < 4; q++) acc[i][j][q] = 0.f;

    int ldr = tid >> 2;                 // 0..63
    int ldcH = (tid & 3) * 8;           // 0,8,16,24

    const __half* aRow0;
    const __half* aRow1;
    if (MODE == 0) {
        aRow0 = A + (size_t)g_idx[m0 + ldr] * K;
        aRow1 = A + (size_t)g_idx[m0 + ldr + 64] * K;
    } else {
        aRow0 = A + (size_t)(m0 + ldr) * K;
        aRow1 = aRow0 + (size_t)64 * K;
    }
    const __half* bRow0 = Bw + (size_t)(n0 + ldr) * K;
    const __half* bRow1 = bRow0 + (size_t)64 * K;

    const int NT = K / 32;

    cpasync16(&Asm[ldr * GROWH + ldcH],        aRow0 + ldcH);
    cpasync16(&Asm[(ldr + 64) * GROWH + ldcH], aRow1 + ldcH);
    cpasync16(&Bsm[ldr * GROWH + ldcH],        bRow0 + ldcH);
    cpasync16(&Bsm[(ldr + 64) * GROWH + ldcH], bRow1 + ldcH);
    cpasync_commit();

    for (int t = 0; t < NT; t++) {
        cpasync_wait0();
        __syncthreads();
        if (t + 1 < NT) {
            int nb = ((t + 1) & 1) * 128 * GROWH;
            int k0 = (t + 1) * 32 + ldcH;
            cpasync16(&Asm[nb + ldr * GROWH + ldcH],        aRow0 + k0);
            cpasync16(&Asm[nb + (ldr + 64) * GROWH + ldcH], aRow1 + k0);
            cpasync16(&Bsm[nb + ldr * GROWH + ldcH],        bRow0 + k0);
            cpasync16(&Bsm[nb + (ldr + 64) * GROWH + ldcH], bRow1 + k0);
            cpasync_commit();
        }
        int cb = (t & 1) * 128 * GROWH;
#pragma unroll
        for (int ks = 0; ks < 2; ks++) {
            int kb = ks * 16;
            uint32_t a[4][4], b[4][2];
#pragma unroll
            for (int i = 0; i < 4; i++) {
                uint32_t ad = asm_u32 + 2u * (cb + (rowA + i * 16) * GROWH + kb + kA);
                ldsm_x4(a[i][0], a[i][1], a[i][2], a[i][3], ad);
            }
#pragma unroll
            for (int p = 0; p < 2; p++) {
                uint32_t ad = bsm_u32 + 2u * (cb + (rowB + p * 16) * GROWH + kb + kB);
                ldsm_x4(b[2 * p][0], b[2 * p][1], b[2 * p + 1][0], b[2 * p + 1][1], ad);
            }
#pragma unroll
            for (int i = 0; i < 4; i++)
#pragma unroll
                for (int j = 0; j < 4; j++)
                    mma_f16(acc[i][j], a[i], b[j]);
        }
    }

#pragma unroll
    for (int j = 0; j < 4; j++) {
        int col = n0 + wn + j * 8 + tig * 2;
        float2 bvv = *(const float2*)(bias_p + col);
#pragma unroll
        for (int i = 0; i < 4; i++) {
            int r = m0 + wm + i * 16 + gid;
            float2 v0 = make_float2(acc[i][j][0] + bvv.x, acc[i][j][1] + bvv.y);
            float2 v1 = make_float2(acc[i][j][2] + bvv.x, acc[i][j][3] + bvv.y);
            *(float2*)(C + (size_t)r * N + col)       = v0;
            *(float2*)(C + (size_t)(r + 8) * N + col) = v1;
        }
    }
}

// ==================== launch 3 (ncu-captured): persistent LSTM ====================
// 128 blocks x 256 thr. Block bx owns h cols [8bx, 8bx+8) = 32 gate-rows.
// W_hh B-frags in regs (fp16). a-frags loaded DIRECTLY from L2 via __ldcg
// (no staging, no bulk copy, no mbarrier): warp w reads only its 10 KB k-slice
// with full MLP; one exposed L2 latency per step.
__global__ __launch_bounds__(256)
void lstm_persistent(const float* __restrict__ Whh,
                     const float* __restrict__ fc_W,
                     const float* __restrict__ fc_b)
{
    __shared__ float red[8 * 32 * 36];   // cross-warp reduction
    __shared__ float gs[32 * 36];

    int tid = threadIdx.x;
    int bx = blockIdx.x;
    int j0 = bx * 8;
    int lane = tid & 31;
    int w = tid >> 5;
    int gid = lane >> 2, tig = lane & 3;
    int bb = tid >> 3, jj = tid & 7;

    // ---- prologue A: W_hh B-fragments -> registers (fp16 pairs) ----
    uint32_t Bf[8][4][2];
#pragma unroll
    for (int s = 0; s < 8; s++) {
#pragma unroll
        for (int nt = 0; nt < 4; nt++) {
            const float* wrow = Whh + (size_t)(nt * Hz + j0 + gid) * Hz + 128 * w + 16 * s + 2 * tig;
            float2 w0 = *(const float2*)(wrow);
            float2 w1 = *(const float2*)(wrow + 8);
            Bf[s][nt][0] = pack_h2(w0.x, w0.y);
            Bf[s][nt][1] = pack_h2(w1.x, w1.y);
        }
    }

    // ---- prologue B: init h0/c0 for this block's columns (warp-coop dots) ----
    for (int oo = 0; oo < 64; oo++) {
        int o = w * 64 + oo;
        int b = o & 31, r = o >> 5;
        int grow = (r < 8) ? (j0 + r) : (Hz + j0 + (r - 8));
        const float4* wp = (const float4*)(fc_W + (size_t)grow * Fz);
        const float4* pp = (const float4*)(g_pooled + (size_t)b * Fz);
        float4 s4 = make_float4(0.f, 0.f, 0.f, 0.f);
        for (int f = lane; f < Fz / 4; f += 32) {
            float4 wv = wp[f];
            float4 pv = pp[f];
            s4.x += wv.x * pv.x; s4.y += wv.y * pv.y;
            s4.z += wv.z * pv.z; s4.w += wv.w * pv.w;
        }
        float v = (s4.x + s4.y) + (s4.z + s4.w);
#pragma unroll
        for (int off = 16; off; off >>= 1) v += __shfl_xor_sync(0xffffffffu, v, off);
        if (lane == 0) {
            v += fc_b[grow];
            if (r < 8) {
                int k = j0 + r;
                __half* hp = (__half*)&g_hTp[0][(k >> 1) * HPS + b];
                hp[k & 1] = __float2half_rn(v);
            } else {
                gs[b * 36 + (r - 8)] = v;
            }
        }
    }
    __syncthreads();
    float c_reg = gs[bb * 36 + jj];

    // grid barrier: all h0 visible
    __threadfence();
    __syncthreads();
    if (tid == 0) atomicExch(&g_flags[bx], 1);
    if (tid < NBLK) {
        while (((volatile int*)g_flags)[tid] < 1) __nanosleep(32);
    }
    __syncthreads();

    // ---- 128 timesteps ----
    for (int t = 0; t < Tz; t++) {
        const __half2* hT_in = g_hTp[t & 1];
        __half2*       hT_out = g_hTp[(t + 1) & 1];

        size_t gbase = ((size_t)bb * Tz + t) * (4 * Hz);
        float xi = __ldcs(&g_xW[gbase + 0 * Hz + j0 + jj]);
        float xf = __ldcs(&g_xW[gbase + 1 * Hz + j0 + jj]);
        float xg = __ldcs(&g_xW[gbase + 2 * Hz + j0 + jj]);
        float xo = __ldcs(&g_xW[gbase + 3 * Hz + j0 + jj]);

        float acc[2][4][4];
#pragma unroll
        for (int mt = 0; mt < 2; mt++)
#pragma unroll
            for (int nt = 0; nt < 4; nt++)
#pragma unroll
                for (int q = 0; q < 4; q++) acc[mt][nt][q] = 0.f;

        // a-frags direct from L2 (warp w's k-slice: kp in [64w, 64w+64))
#pragma unroll
        for (int s = 0; s < 8; s++) {
            int kpb = 64 * w + 8 * s;
            uint32_t a[2][4];
#pragma unroll
            for (int mt = 0; mt < 2; mt++) {
                int m = mt * 16 + gid;
                const unsigned int* b0 = (const unsigned int*)(hT_in + (kpb + tig) * HPS + m);
                const unsigned int* b4 = (const unsigned int*)(hT_in + (kpb + tig + 4) * HPS + m);
                a[mt][0] = __ldcg(b0);
                a[mt][1] = __ldcg(b0 + 8);
                a[mt][2] = __ldcg(b4);
                a[mt][3] = __ldcg(b4 + 8);
            }
#pragma unroll
            for (int nt = 0; nt < 4; nt++) {
                mma_f16(acc[0][nt], a[0], Bf[s][nt]);
                mma_f16(acc[1][nt], a[1], Bf[s][nt]);
            }
        }

        // ---- cross-warp reduction ----
        __syncthreads();
#pragma unroll
        for (int mt = 0; mt < 2; mt++) {
#pragma unroll
            for (int nt = 0; nt < 4; nt++) {
                int row0 = mt * 16 + gid;
                int n = nt * 8 + 2 * tig;
                *(float2*)(red + (w * 32 + row0) * 36 + n) =
                    make_float2(acc[mt][nt][0], acc[mt][nt][1]);
                *(float2*)(red + (w * 32 + row0 + 8) * 36 + n) =
                    make_float2(acc[mt][nt][2], acc[mt][nt][3]);
            }
        }
        __syncthreads();
        {
            int b = tid >> 3, n4 = (tid & 7) * 4;
            float4 sum = make_float4(0.f, 0.f, 0.f, 0.f);
#pragma unroll
            for (int ww = 0; ww < 8; ww++) {
                float4 v = *(const float4*)(red + (ww * 32 + b) * 36 + n4);
                sum.x += v.x; sum.y += v.y; sum.z += v.z; sum.w += v.w;
            }
            *(float4*)(gs + b * 36 + n4) = sum;
        }
        __syncthreads();

        // ---- elementwise gate update ----
        float gi = gs[bb * 36 +  0 + jj] + xi;
        float gf = gs[bb * 36 +  8 + jj] + xf;
        float gg = gs[bb * 36 + 16 + jj] + xg;
        float go = gs[bb * 36 + 24 + jj] + xo;

        float cn = sigmoidf_(gf) * c_reg + sigmoidf_(gi) * tanhf(gg);
        float hn = sigmoidf_(go) * tanhf(cn);
        c_reg = cn;
        __half hr16 = __float2half_rn(hn);
        {
            int k = j0 + jj;
            __half* hp = (__half*)&hT_out[(k >> 1) * HPS + bb];
            hp[k & 1] = hr16;
            g_hs16[((size_t)bb * Tz + t) * Hz + k] = hr16;
        }

        // ---- grid barrier ----
        __threadfence();
        __syncthreads();
        if (tid == 0) atomicExch(&g_flags[bx], t + 2);
        if (tid < NBLK) {
            while (((volatile int*)g_flags)[tid] < t + 2) __nanosleep(32);
        }
        __syncthreads();
    }
}

// ==================== launcher ====================
extern "C" void kernel_launch(void* const* d_in, const int* in_sizes, int n_in,
                              void* d_out, int out_size) {
    const float* features = (const float*)d_in[0];
    const int*   reports  = (const int*)d_in[1];
    const float* fc_W     = (const float*)d_in[2];
    const float* fc_b     = (const float*)d_in[3];
    const float* emb      = (const float*)d_in[4];
    const float* W_ih     = (const float*)d_in[5];
    const float* W_hh     = (const float*)d_in[6];
    const float* b_ih     = (const float*)d_in[7];
    const float* b_hh     = (const float*)d_in[8];
    const float* Wv       = (const float*)d_in[9];
    const float* bv       = (const float*)d_in[10];
    float* out = (float*)d_out;

    (void)in_sizes; (void)n_in; (void)out_size;

    cudaFuncSetAttribute(gemm_f16_kernel<0>,
                         cudaFuncAttributeMaxDynamicSharedMemorySize, (int)GEMM_SMEM);
    cudaFuncSetAttribute(gemm_f16_kernel<1>,
                         cudaFuncAttributeMaxDynamicSharedMemorySize, (int)GEMM_SMEM);

    // launch 0: fused prep (pool + idx + bias + flags)
    prep_kernel<<<(Bz * Fz + 255) / 256, 256>>>(features, reports, b_ih, b_hh);

    // launch 1: fp32 -> fp16 conversion (Wv, emb, W_ih)
    {
        int n = (Vz * Hz + Vz * Ez + 4 * Hz * Ez) / 4;
        round_all_kernel<<<(n + 255) / 256, 256>>>((const float4*)Wv,
                                                   (const float4*)emb,
                                                   (const float4*)W_ih);
    }

    // launch 2: input GEMM  xW = emb[idx] @ W_ih^T + (b_ih + b_hh)
    gemm_f16_kernel<0><<<dim3(Bz * Tz / 128, 4 * Hz / 128), 256, GEMM_SMEM>>>(nullptr, nullptr);

    // launch 3 (ncu-captured): persistent LSTM (init + 128 timesteps)
    lstm_persistent<<<NBLK, 256>>>(W_hh, fc_W, fc_b);

    // launch 4: projection  out = hs @ Wv^T + bv
    gemm_f16_kernel<1><<<dim3(Bz * Tz / 128, Vz / 128), 256, GEMM_SMEM>>>(bv, out);
}

// round 14
// speedup vs baseline: 2.5093x; 1.1017x over previous
#include <cuda_runtime.h>
#include <cuda_fp16.h>
#include <math.h>
#include <stdint.h>

#define Bz 32
#define Tz 128
#define Vz 16000
#define Ez 512
#define Hz 1024
#define Fz 2048
#define NBLK 128
#define HPS 40                             // half2-row stride for hTp (conflict-free)

// -------- scratch (static device globals; no runtime allocation) --------
__device__ float   g_pooled[Bz * Fz];
__device__ __half2 g_hTp[2][(Hz / 2) * HPS];   // transposed h ping-pong: [kp][b] fp16 pairs
__device__ float   g_xW[Bz * Tz * 4 * Hz];     // input-gate preactivations (fp32)
__device__ __half  g_hs16[Bz * Tz * Hz];       // hidden states fp16 (proj A)
__device__ __half  g_Wv16[Vz * Hz];
__device__ __half  g_embt16[Vz * Ez];
__device__ __half  g_Wih16[4 * Hz * Ez];
__device__ float   g_bihh[4 * Hz];             // b_ih + b_hh
__device__ int     g_idx[Bz * Tz];
__device__ int     g_flags[NBLK];

__device__ __forceinline__ float sigmoidf_(float x) {
    return 1.0f / (1.0f + expf(-x));
}
__device__ __forceinline__ uint32_t pack_h2(float x, float y) {
    __half2 h = __float22half2_rn(make_float2(x, y));
    return *reinterpret_cast<uint32_t*>(&h);
}
__device__ __forceinline__ void cpasync16(void* dst, const void* src) {
    uint32_t d = (uint32_t)__cvta_generic_to_shared(dst);
    asm volatile("cp.async.cg.shared.global [%0], [%1], 16;" :: "r"(d), "l"(src));
}
__device__ __forceinline__ void cpasync_commit() { asm volatile("cp.async.commit_group;"); }
__device__ __forceinline__ void cpasync_wait0()  { asm volatile("cp.async.wait_group 0;"); }

__device__ __forceinline__ void mma_f16(float* c, const uint32_t* a, const uint32_t* b) {
    asm volatile(
        "mma.sync.aligned.m16n8k16.row.col.f32.f16.f16.f32 "
        "{%0,%1,%2,%3}, {%4,%5,%6,%7}, {%8,%9}, {%0,%1,%2,%3};"
        : "+f"(c[0]), "+f"(c[1]), "+f"(c[2]), "+f"(c[3])
        : "r"(a[0]), "r"(a[1]), "r"(a[2]), "r"(a[3]), "r"(b[0]), "r"(b[1]));
}
__device__ __forceinline__ void ldsm_x4(uint32_t& r0, uint32_t& r1, uint32_t& r2, uint32_t& r3,
                                        uint32_t addr) {
    asm volatile("ldmatrix.sync.aligned.m8n8.x4.shared.b16 {%0,%1,%2,%3}, [%4];"
                 : "=r"(r0), "=r"(r1), "=r"(r2), "=r"(r3) : "r"(addr));
}

// ---- mbarrier + bulk-copy helpers ----
__device__ __forceinline__ void mbar_init(uint32_t a, uint32_t cnt) {
    asm volatile("mbarrier.init.shared.b64 [%0], %1;" :: "r"(a), "r"(cnt) : "memory");
}
__device__ __forceinline__ void mbar_expect_tx(uint32_t a, uint32_t bytes) {
    asm volatile("mbarrier.arrive.expect_tx.shared.b64 _, [%0], %1;"
                 :: "r"(a), "r"(bytes) : "memory");
}
__device__ __forceinline__ void mbar_wait_parity(uint32_t a, uint32_t parity) {
    uint32_t done;
    asm volatile(
        "{\n\t.reg .pred p;\n\t"
        "mbarrier.try_wait.parity.acquire.cta.shared::cta.b64 p, [%1], %2;\n\t"
        "selp.b32 %0, 1, 0, p;\n\t}"
        : "=r"(done) : "r"(a), "r"(parity) : "memory");
    if (!done) {
        asm volatile(
            "{\n\t.reg .pred P1;\n\t"
            "WL_%=:\n\t"
            "mbarrier.try_wait.parity.acquire.cta.shared::cta.b64 P1, [%0], %1, 0x989680;\n\t"
            "@P1 bra.uni WD_%=;\n\t"
            "bra.uni WL_%=;\n\t"
            "WD_%=:\n\t}"
            :: "r"(a), "r"(parity) : "memory");
    }
}
__device__ __forceinline__ void bulk_g2s(uint32_t dst_smem, const void* src,
                                         uint32_t bytes, uint32_t mbar) {
    asm volatile(
        "cp.async.bulk.shared::cta.global.mbarrier::complete_tx::bytes [%0], [%1], %2, [%3];"
        :: "r"(dst_smem), "l"(src), "r"(bytes), "r"(mbar) : "memory");
}

// ==================== launch 0: fused small prep ====================
__global__ void prep_kernel(const float* __restrict__ features,
                            const int* __restrict__ reports,
                            const float* __restrict__ b_ih,
                            const float* __restrict__ b_hh) {
    int n = blockIdx.x * blockDim.x + threadIdx.x;   // 65536 threads
    if (n < Bz * Fz) {
        const float* p = features + (size_t)n * 49;
        float s = 0.f;
#pragma unroll
        for (int i = 0; i < 49; i++) s += p[i];
        g_pooled[n] = s * (1.0f / 49.0f);
    }
    if (n < Bz * Tz) {
        int t = n & (Tz - 1);
        g_idx[n] = (t == 0) ? 1 : reports[n - 1];    // START_IDX = 1
    }
    if (n < 4 * Hz) g_bihh[n] = b_ih[n] + b_hh[n];
    if (n < NBLK) g_flags[n] = 0;
}

// ==================== launch 1: fp32 -> fp16 conversion ====================
__global__ void round_all_kernel(const float4* __restrict__ Wv,
                                 const float4* __restrict__ emb,
                                 const float4* __restrict__ Wih) {
    int i = blockIdx.x * blockDim.x + threadIdx.x;
    const int n1 = Vz * Hz / 4, n2 = Vz * Ez / 4, n3 = 4 * Hz * Ez / 4;
    const float4* src;
    __half* dst;
    if (i < n1)              { src = Wv;  dst = g_Wv16;  }
    else if ((i -= n1) < n2) { src = emb; dst = g_embt16; }
    else if ((i -= n2) < n3) { src = Wih; dst = g_Wih16; }
    else return;
    float4 v = src[i];
    uint2 pk = make_uint2(pack_h2(v.x, v.y), pack_h2(v.z, v.w));
    *(uint2*)(dst + 4 * (size_t)i) = pk;
}

// ==================== fp16 tensor-core GEMM (launches 2 and 4), ldmatrix frags ====
#define GROWH 40
#define GEMM_SMEM (size_t)(4 * 128 * GROWH * sizeof(__half))   // 40 KB

template<int MODE>
__global__ __launch_bounds__(256)
void gemm_f16_kernel(const float* __restrict__ bias, float* __restrict__ outp)
{
    extern __shared__ __half gsm[];
    __half* Asm = gsm;                        // [2][128*GROWH]
    __half* Bsm = gsm + 2 * 128 * GROWH;      // [2][128*GROWH]

    constexpr int K = (MODE == 0) ? Ez : Hz;
    constexpr int N = (MODE == 0) ? 4 * Hz : Vz;
    const __half* A  = (MODE == 0) ? g_embt16 : g_hs16;
    const __half* Bw = (MODE == 0) ? g_Wih16 : g_Wv16;
    float* C         = (MODE == 0) ? g_xW : outp;
    const float* bias_p = (MODE == 0) ? g_bihh : bias;

    int tid = threadIdx.x;
    int m0 = blockIdx.x * 128;
    int n0 = blockIdx.y * 128;

    int wid = tid >> 5, lane = tid & 31;
    int wm = (wid >> 2) * 64;
    int wn = (wid & 3) * 32;
    int gid = lane >> 2, tig = lane & 3;

    // ldmatrix per-lane row/col offsets
    int mat = lane >> 3, lr = lane & 7;
    int rowA = wm + (mat & 1) * 8 + lr;       // + i*16
    int kA   = (mat >> 1) * 8;
    int rowB = wn + (mat >> 1) * 8 + lr;      // + p*16
    int kB   = (mat & 1) * 8;
    uint32_t asm_u32 = (uint32_t)__cvta_generic_to_shared(Asm);
    uint32_t bsm_u32 = (uint32_t)__cvta_generic_to_shared(Bsm);

    float acc[4][4][4];
#pragma unroll
    for (int i = 0; i < 4; i++)
#pragma unroll
        for (int j = 0; j < 4; j++)
#pragma unroll
            for (int q = 0; q < 4; q++) acc[i][j][q] = 0.f;

    int ldr = tid >> 2;                 // 0..63
    int ldcH = (tid & 3) * 8;           // 0,8,16,24

    const __half* aRow0;
    const __half* aRow1;
    if (MODE == 0) {
        aRow0 = A + (size_t)g_idx[m0 + ldr] * K;
        aRow1 = A + (size_t)g_idx[m0 + ldr + 64] * K;
    } else {
        aRow0 = A + (size_t)(m0 + ldr) * K;
        aRow1 = aRow0 + (size_t)64 * K;
    }
    const __half* bRow0 = Bw + (size_t)(n0 + ldr) * K;
    const __half* bRow1 = bRow0 + (size_t)64 * K;

    const int NT = K / 32;

    cpasync16(&Asm[ldr * GROWH + ldcH],        aRow0 + ldcH);
    cpasync16(&Asm[(ldr + 64) * GROWH + ldcH], aRow1 + ldcH);
    cpasync16(&Bsm[ldr * GROWH + ldcH],        bRow0 + ldcH);
    cpasync16(&Bsm[(ldr + 64) * GROWH + ldcH], bRow1 + ldcH);
    cpasync_commit();

    for (int t = 0; t < NT; t++) {
        cpasync_wait0();
        __syncthreads();
        if (t + 1 < NT) {
            int nb = ((t + 1) & 1) * 128 * GROWH;
            int k0 = (t + 1) * 32 + ldcH;
            cpasync16(&Asm[nb + ldr * GROWH + ldcH],        aRow0 + k0);
            cpasync16(&Asm[nb + (ldr + 64) * GROWH + ldcH], aRow1 + k0);
            cpasync16(&Bsm[nb + ldr * GROWH + ldcH],        bRow0 + k0);
            cpasync16(&Bsm[nb + (ldr + 64) * GROWH + ldcH], bRow1 + k0);
            cpasync_commit();
        }
        int cb = (t & 1) * 128 * GROWH;
#pragma unroll
        for (int ks = 0; ks < 2; ks++) {
            int kb = ks * 16;
            uint32_t a[4][4], b[4][2];
#pragma unroll
            for (int i = 0; i < 4; i++) {
                uint32_t ad = asm_u32 + 2u * (cb + (rowA + i * 16) * GROWH + kb + kA);
                ldsm_x4(a[i][0], a[i][1], a[i][2], a[i][3], ad);
            }
#pragma unroll
            for (int p = 0; p < 2; p++) {
                uint32_t ad = bsm_u32 + 2u * (cb + (rowB + p * 16) * GROWH + kb + kB);
                ldsm_x4(b[2 * p][0], b[2 * p][1], b[2 * p + 1][0], b[2 * p + 1][1], ad);
            }
#pragma unroll
            for (int i = 0; i < 4; i++)
#pragma unroll
                for (int j = 0; j < 4; j++)
                    mma_f16(acc[i][j], a[i], b[j]);
        }
    }

#pragma unroll
    for (int j = 0; j < 4; j++) {
        int col = n0 + wn + j * 8 + tig * 2;
        float2 bvv = *(const float2*)(bias_p + col);
#pragma unroll
        for (int i = 0; i < 4; i++) {
            int r = m0 + wm + i * 16 + gid;
            float2 v0 = make_float2(acc[i][j][0] + bvv.x, acc[i][j][1] + bvv.y);
            float2 v1 = make_float2(acc[i][j][2] + bvv.x, acc[i][j][3] + bvv.y);
            *(float2*)(C + (size_t)r * N + col)       = v0;
            *(float2*)(C + (size_t)(r + 8) * N + col) = v1;
        }
    }
}

// ==================== launch 3 (ncu-captured): persistent LSTM (R11 staging) ====
// 128 blocks x 256 thr. Block bx owns h cols [8bx, 8bx+8) = 32 gate-rows.
// W_hh B-frags in regs (fp16 pairs). h exchanged as half2[kp][b] stride HPS=40;
// per step ONE 80 KB volley as 8 chunked cp.async.bulk + per-chunk mbarriers;
// warp w waits only its own 10 KB k-slice. a-frag smem reads conflict-free.
#define HT_BYTES ((Hz / 2) * HPS * 4)          // 81920
#define CHUNK_BYTES (HT_BYTES / 8)             // 10240
#define SMEM_LSTM (size_t)(HT_BYTES + (9216 + 1152) * 4 + 64)

__global__ __launch_bounds__(256)
void lstm_persistent(const float* __restrict__ Whh,
                     const float* __restrict__ fc_W,
                     const float* __restrict__ fc_b)
{
    extern __shared__ char smraw[];
    __half2* hsm2 = (__half2*)smraw;                       // [(Hz/2)*HPS]
    float* red = (float*)(smraw + HT_BYTES);               // [8][32][36]
    float* gs  = (float*)(smraw + HT_BYTES + 9216 * 4);    // [32][36]
    uint32_t smem_base = (uint32_t)__cvta_generic_to_shared(smraw);
    uint32_t hsm_u32  = smem_base;
    uint32_t mbar_u32 = smem_base + HT_BYTES + (9216 + 1152) * 4;  // 8 mbarriers

    int tid = threadIdx.x;
    int bx = blockIdx.x;
    int j0 = bx * 8;
    int lane = tid & 31;
    int w = tid >> 5;
    int gid = lane >> 2, tig = lane & 3;
    int bb = tid >> 3, jj = tid & 7;

    if (tid < 8) mbar_init(mbar_u32 + 8 * tid, 1);

    // ---- prologue A: W_hh B-fragments -> registers (fp16 pairs) ----
    uint32_t Bf[8][4][2];
#pragma unroll
    for (int s = 0; s < 8; s++) {
#pragma unroll
        for (int nt = 0; nt < 4; nt++) {
            const float* wrow = Whh + (size_t)(nt * Hz + j0 + gid) * Hz + 128 * w + 16 * s + 2 * tig;
            float2 w0 = *(const float2*)(wrow);
            float2 w1 = *(const float2*)(wrow + 8);
            Bf[s][nt][0] = pack_h2(w0.x, w0.y);
            Bf[s][nt][1] = pack_h2(w1.x, w1.y);
        }
    }

    // ---- prologue B: init h0/c0 for this block's columns (warp-coop dots) ----
    for (int oo = 0; oo < 64; oo++) {
        int o = w * 64 + oo;
        int b = o & 31, r = o >> 5;
        int grow = (r < 8) ? (j0 + r) : (Hz + j0 + (r - 8));
        const float4* wp = (const float4*)(fc_W + (size_t)grow * Fz);
        const float4* pp = (const float4*)(g_pooled + (size_t)b * Fz);
        float4 s4 = make_float4(0.f, 0.f, 0.f, 0.f);
        for (int f = lane; f < Fz / 4; f += 32) {
            float4 wv = wp[f];
            float4 pv = pp[f];
            s4.x += wv.x * pv.x; s4.y += wv.y * pv.y;
            s4.z += wv.z * pv.z; s4.w += wv.w * pv.w;
        }
        float v = (s4.x + s4.y) + (s4.z + s4.w);
#pragma unroll
        for (int off = 16; off; off >>= 1) v += __shfl_xor_sync(0xffffffffu, v, off);
        if (lane == 0) {
            v += fc_b[grow];
            if (r < 8) {
                int k = j0 + r;
                __half* hp = (__half*)&g_hTp[0][(k >> 1) * HPS + b];
                hp[k & 1] = __float2half_rn(v);
            } else {
                gs[b * 36 + (r - 8)] = v;
            }
        }
    }
    __syncthreads();
    float c_reg = gs[bb * 36 + jj];

    // grid barrier: all h0 visible
    __threadfence();
    __syncthreads();
    if (tid == 0) atomicExch(&g_flags[bx], 1);
    if (tid < NBLK) {
        while (((volatile int*)g_flags)[tid] < 1) __nanosleep(32);
    }
    __syncthreads();

    // ---- 128 timesteps ----
    for (int t = 0; t < Tz; t++) {
        const __half2* hT_in = g_hTp[t & 1];
        __half2*       hT_out = g_hTp[(t + 1) & 1];

        size_t gbase = ((size_t)bb * Tz + t) * (4 * Hz);
        float xi = __ldcs(&g_xW[gbase + 0 * Hz + j0 + jj]);
        float xf = __ldcs(&g_xW[gbase + 1 * Hz + j0 + jj]);
        float xg = __ldcs(&g_xW[gbase + 2 * Hz + j0 + jj]);
        float xo = __ldcs(&g_xW[gbase + 3 * Hz + j0 + jj]);

        // stage hTp: 8 chunked bulk copies (10 KB each), per-chunk mbarrier
        if (tid == 0) {
#pragma unroll
            for (int i = 0; i < 8; i++) {
                mbar_expect_tx(mbar_u32 + 8 * i, (uint32_t)CHUNK_BYTES);
                bulk_g2s(hsm_u32 + i * CHUNK_BYTES,
                         (const char*)hT_in + i * CHUNK_BYTES,
                         CHUNK_BYTES, mbar_u32 + 8 * i);
            }
        }
        // warp w waits only for its own k-slice (chunk w: kp in [64w, 64w+64))
        mbar_wait_parity(mbar_u32 + 8 * w, t & 1);

        float acc[2][4][4];
#pragma unroll
        for (int mt = 0; mt < 2; mt++)
#pragma unroll
            for (int nt = 0; nt < 4; nt++)
#pragma unroll
                for (int q = 0; q < 4; q++) acc[mt][nt][q] = 0.f;

#pragma unroll
        for (int s = 0; s < 8; s++) {
            int kpb = 64 * w + 8 * s;
            uint32_t a[2][4];
#pragma unroll
            for (int mt = 0; mt < 2; mt++) {
                int m = mt * 16 + gid;
                a[mt][0] = *(const uint32_t*)(&hsm2[(kpb + tig) * HPS + m]);
                a[mt][1] = *(const uint32_t*)(&hsm2[(kpb + tig) * HPS + m + 8]);
                a[mt][2] = *(const uint32_t*)(&hsm2[(kpb + tig + 4) * HPS + m]);
                a[mt][3] = *(const uint32_t*)(&hsm2[(kpb + tig + 4) * HPS + m + 8]);
            }
#pragma unroll
            for (int nt = 0; nt < 4; nt++) {
                mma_f16(acc[0][nt], a[0], Bf[s][nt]);
                mma_f16(acc[1][nt], a[1], Bf[s][nt]);
            }
        }

        // ---- cross-warp reduction ----
        // (no sync needed before red writes: each warp's region is disjoint, and
        //  previous-iteration reads are fenced by the grid barrier's syncs)
#pragma unroll
        for (int mt = 0; mt < 2; mt++) {
#pragma unroll
            for (int nt = 0; nt < 4; nt++) {
                int row0 = mt * 16 + gid;
                int n = nt * 8 + 2 * tig;
                *(float2*)(red + (w * 32 + row0) * 36 + n) =
                    make_float2(acc[mt][nt][0], acc[mt][nt][1]);
                *(float2*)(red + (w * 32 + row0 + 8) * 36 + n) =
                    make_float2(acc[mt][nt][2], acc[mt][nt][3]);
            }
        }
        __syncthreads();
        {
            int b = tid >> 3, n4 = (tid & 7) * 4;
            float4 sum = make_float4(0.f, 0.f, 0.f, 0.f);
#pragma unroll
            for (int ww = 0; ww < 8; ww++) {
                float4 v = *(const float4*)(red + (ww * 32 + b) * 36 + n4);
                sum.x += v.x; sum.y += v.y; sum.z += v.z; sum.w += v.w;
            }
            *(float4*)(gs + b * 36 + n4) = sum;
        }
        __syncthreads();

        // ---- elementwise gate update ----
        float gi = gs[bb * 36 +  0 + jj] + xi;
        float gf = gs[bb * 36 +  8 + jj] + xf;
        float gg = gs[bb * 36 + 16 + jj] + xg;
        float go = gs[bb * 36 + 24 + jj] + xo;

        float cn = sigmoidf_(gf) * c_reg + sigmoidf_(gi) * tanhf(gg);
        float hn = sigmoidf_(go) * tanhf(cn);
        c_reg = cn;
        __half hr16 = __float2half_rn(hn);
        {
            int k = j0 + jj;
            __half* hp = (__half*)&hT_out[(k >> 1) * HPS + bb];
            hp[k & 1] = hr16;
            g_hs16[((size_t)bb * Tz + t) * Hz + k] = hr16;
        }

        // ---- grid barrier ----
        __threadfence();
        __syncthreads();
        if (tid == 0) atomicExch(&g_flags[bx], t + 2);
        if (tid < NBLK) {
            while (((volatile int*)g_flags)[tid] < t + 2) __nanosleep(32);
        }
        __syncthreads();
    }
}

// ==================== launcher ====================
extern "C" void kernel_launch(void* const* d_in, const int* in_sizes, int n_in,
                              void* d_out, int out_size) {
    const float* features = (const float*)d_in[0];
    const int*   reports  = (const int*)d_in[1];
    const float* fc_W     = (const float*)d_in[2];
    const float* fc_b     = (const float*)d_in[3];
    const float* emb      = (const float*)d_in[4];
    const float* W_ih     = (const float*)d_in[5];
    const float* W_hh     = (const float*)d_in[6];
    const float* b_ih     = (const float*)d_in[7];
    const float* b_hh     = (const float*)d_in[8];
    const float* Wv       = (const float*)d_in[9];
    const float* bv       = (const float*)d_in[10];
    float* out = (float*)d_out;

    (void)in_sizes; (void)n_in; (void)out_size;

    cudaFuncSetAttribute(lstm_persistent,
                         cudaFuncAttributeMaxDynamicSharedMemorySize, (int)SMEM_LSTM);
    cudaFuncSetAttribute(gemm_f16_kernel<0>,
                         cudaFuncAttributeMaxDynamicSharedMemorySize, (int)GEMM_SMEM);
    cudaFuncSetAttribute(gemm_f16_kernel<1>,
                         cudaFuncAttributeMaxDynamicSharedMemorySize, (int)GEMM_SMEM);

    // launch 0: fused prep (pool + idx + bias + flags)
    prep_kernel<<<(Bz * Fz + 255) / 256, 256>>>(features, reports, b_ih, b_hh);

    // launch 1: fp32 -> fp16 conversion (Wv, emb, W_ih)
    {
        int n = (Vz * Hz + Vz * Ez + 4 * Hz * Ez) / 4;
        round_all_kernel<<<(n + 255) / 256, 256>>>((const float4*)Wv,
                                                   (const float4*)emb,
                                                   (const float4*)W_ih);
    }

    // launch 2: input GEMM  xW = emb[idx] @ W_ih^T + (b_ih + b_hh)
    gemm_f16_kernel<0><<<dim3(Bz * Tz / 128, 4 * Hz / 128), 256, GEMM_SMEM>>>(nullptr, nullptr);

    // launch 3 (ncu-captured): persistent LSTM (init + 128 timesteps)
    lstm_persistent<<<NBLK, 256, SMEM_LSTM>>>(W_hh, fc_W, fc_b);

    // launch 4: projection  out = hs @ Wv^T + bv
    gemm_f16_kernel<1><<<dim3(Bz * Tz / 128, Vz / 128), 256, GEMM_SMEM>>>(bv, out);
}